// round 14
// baseline (speedup 1.0000x reference)
#include <cuda_runtime.h>
#include <cuda_bf16.h>
#include <cstdint>

#define Bo 96
#define To 100
#define Do 1024
#define Bw 96
#define Tw 30
#define Dw 768
#define Du 2048
#define Dk 256
#define Dv 256

typedef __nv_bfloat16 bf16;

// ---------------- scratch ----------------
__device__ __align__(256) bf16 Wkuhi_g[Du * Dk], Wkulo_g[Du * Dk];     // [K][N]
__device__ __align__(256) bf16 Wkwhi_g[Dw * Dk], Wkwlo_g[Dw * Dk];
__device__ __align__(256) bf16 Wfohi_g[Do * Dv], Wfolo_g[Do * Dv];
__device__ __align__(256) bf16 Wfwhi_g[Dw * Dv], Wfwlo_g[Dw * Dv];
__device__ __align__(256) bf16 Kuhi_g[(size_t)Bo * To * Dk], Kulo_g[(size_t)Bo * To * Dk];
__device__ __align__(256) bf16 Kwhi_g[(size_t)Bw * Tw * Dk], Kwlo_g[(size_t)Bw * Tw * Dk];
__device__ __align__(256) bf16 Vohi_g[(size_t)Bo * 128 * Dv], Volo_g[(size_t)Bo * 128 * Dv]; // o pad 128
__device__ __align__(256) float Vw_g[(size_t)Bw * Tw * Dv];
__device__ __align__(256) float S_g[(size_t)Bw * Tw * Bo * To];
__device__ __align__(256) float logits_g[(size_t)Bw * Bo * Tw];
__device__ __align__(256) float terms_g[(size_t)Bw * Tw];

// ---------------- helpers ----------------
__device__ __forceinline__ void ldsm_x4(uint32_t* r, uint32_t addr) {
    asm volatile("ldmatrix.sync.aligned.m8n8.x4.shared.b16 {%0,%1,%2,%3},[%4];"
                 : "=r"(r[0]), "=r"(r[1]), "=r"(r[2]), "=r"(r[3]) : "r"(addr));
}
__device__ __forceinline__ void ldsm_x4t(uint32_t* r, uint32_t addr) {
    asm volatile("ldmatrix.sync.aligned.m8n8.x4.trans.shared.b16 {%0,%1,%2,%3},[%4];"
                 : "=r"(r[0]), "=r"(r[1]), "=r"(r[2]), "=r"(r[3]) : "r"(addr));
}
__device__ __forceinline__ void mma16816(float* c, const uint32_t* a, uint32_t b0, uint32_t b1) {
    asm volatile("mma.sync.aligned.m16n8k16.row.col.f32.bf16.bf16.f32 "
                 "{%0,%1,%2,%3},{%4,%5,%6,%7},{%8,%9},{%0,%1,%2,%3};"
                 : "+f"(c[0]), "+f"(c[1]), "+f"(c[2]), "+f"(c[3])
                 : "r"(a[0]), "r"(a[1]), "r"(a[2]), "r"(a[3]), "r"(b0), "r"(b1));
}
__device__ __forceinline__ void cp16(uint32_t dst, const void* src) {
    asm volatile("cp.async.cg.shared.global [%0],[%1],16;" :: "r"(dst), "l"(src));
}
#define CP_COMMIT() asm volatile("cp.async.commit_group;")
#define CP_WAIT1()  asm volatile("cp.async.wait_group 1;")
#define CP_WAIT0()  asm volatile("cp.async.wait_group 0;")

__device__ __forceinline__ uint32_t pack2(float a, float b) {
    __nv_bfloat162 v = __floats2bfloat162_rn(a, b);
    return *(uint32_t*)&v;
}
__device__ __forceinline__ void split8(const float* f, uint32_t* hi, uint32_t* lo) {
#pragma unroll
    for (int j = 0; j < 4; j++) {
        bf16 h0 = __float2bfloat16(f[2 * j]);
        bf16 h1 = __float2bfloat16(f[2 * j + 1]);
        __nv_bfloat162 hv; hv.x = h0; hv.y = h1;
        hi[j] = *(uint32_t*)&hv;
        lo[j] = pack2(f[2 * j] - __bfloat162float(h0), f[2 * j + 1] - __bfloat162float(h1));
    }
}

// ---------------- merged weight split ----------------
#define N1 (Du * Dk / 4)
#define N2 (N1 + Dw * Dk / 4)
#define N3 (N2 + Do * Dv / 4)
#define N4 (N3 + Dw * Dv / 4)
__global__ __launch_bounds__(256) void split_all_k(
    const float* __restrict__ Wku, const float* __restrict__ Wkw,
    const float* __restrict__ Wfo, const float* __restrict__ Wfw)
{
    int i = blockIdx.x * 256 + threadIdx.x;
    if (i >= N4) return;
    const float* src; bf16 *hi, *lo; int j;
    if (i < N1)      { src = Wku; hi = Wkuhi_g; lo = Wkulo_g; j = i; }
    else if (i < N2) { src = Wkw; hi = Wkwhi_g; lo = Wkwlo_g; j = i - N1; }
    else if (i < N3) { src = Wfo; hi = Wfohi_g; lo = Wfolo_g; j = i - N2; }
    else             { src = Wfw; hi = Wfwhi_g; lo = Wfwlo_g; j = i - N3; }
    float4 v = ((const float4*)src)[j];
    float f[4] = {v.x, v.y, v.z, v.w};
    uint32_t h[2], l[2];
#pragma unroll
    for (int q = 0; q < 2; q++) {
        bf16 h0 = __float2bfloat16(f[2 * q]), h1 = __float2bfloat16(f[2 * q + 1]);
        __nv_bfloat162 hv; hv.x = h0; hv.y = h1;
        h[q] = *(uint32_t*)&hv;
        l[q] = pack2(f[2 * q] - __bfloat162float(h0), f[2 * q + 1] - __bfloat162float(h1));
    }
    ((uint32_t*)hi)[j * 2] = h[0]; ((uint32_t*)hi)[j * 2 + 1] = h[1];
    ((uint32_t*)lo)[j * 2] = l[0]; ((uint32_t*)lo)[j * 2 + 1] = l[1];
}

__global__ __launch_bounds__(1024) void zero_logits_k() {
    logits_g[blockIdx.x * 1024 + threadIdx.x] = 0.f;
}

// =====================================================================
// Projection GEMM, grouped for stream overlap, INTERLEAVED hi/lo smem:
//   A stage: 128 rows x [hi32|lo32|pad8]  (72 elems, 144B stride)
//   B stage: 32 k-rows x [hi128|lo128|pad8] (264 elems, 528B stride)
// smem = (3*9216 + 3*8448)*2 = 105984 B -> 2 CTAs/SM fits.
// grp 0: bid<150 -> Ku (K=2048); else Kw (K=768). grp 1: Vo / Vw.
// =====================================================================
#define PAST 9216
#define PBST 8448
#define PBBASE (3 * PAST)
#define PROJ_SMEM ((3 * PAST + 3 * PBST) * 2)   // 105984 B

__global__ __launch_bounds__(256, 2) void proj_grp_k(
    const float* __restrict__ u, const float* __restrict__ o, const float* __restrict__ w,
    const float* __restrict__ bku, const float* __restrict__ bkw,
    const float* __restrict__ bfo, const float* __restrict__ bfw,
    const int grp)
{
    extern __shared__ bf16 dyns[];
    const uint32_t sbase = (uint32_t)__cvta_generic_to_shared(dyns);
    const int N = 256;
    const int tid = threadIdx.x, lane = tid & 31, w8 = tid >> 5;
    const int wm = w8 & 3, wn = w8 >> 2;
    const int bid = blockIdx.x;

    const float* A; const bf16 *bhi, *blo; const float* bs;
    bf16 *Chi = nullptr, *Clo = nullptr; float* Cf = nullptr;
    int M, K, n0, m0, remap = 0; bool splitOut;

    if (bid < 150) {
        n0 = (bid & 1) * 128; m0 = (bid >> 1) * 128; M = Bo * To;
        if (grp == 0) {
            A = u; K = Du; bhi = Wkuhi_g; blo = Wkulo_g; bs = bku;
            Chi = Kuhi_g; Clo = Kulo_g; splitOut = true;
        } else {
            A = o; K = Do; bhi = Wfohi_g; blo = Wfolo_g; bs = bfo;
            Chi = Vohi_g; Clo = Volo_g; splitOut = true; remap = 1;
        }
    } else {
        int b2 = bid - 150;             // 0..45
        n0 = (b2 & 1) * 128; m0 = (b2 >> 1) * 128;
        A = w; K = Dw; M = Bw * Tw;
        if (grp == 0) {
            bhi = Wkwhi_g; blo = Wkwlo_g; bs = bkw;
            Chi = Kwhi_g; Clo = Kwlo_g; splitOut = true;
        } else {
            bhi = Wfwhi_g; blo = Wfwlo_g; bs = bfw; Cf = Vw_g; splitOut = false;
        }
    }

    const int akq = tid & 3, aml = tid >> 2;
    size_t abase[2];
#pragma unroll
    for (int p = 0; p < 2; p++) {
        int m = m0 + p * 64 + aml;
        if (m >= M) m = M - 1;
        abase[p] = (size_t)m * K;
    }
    const int bkr = tid >> 4, bnq = tid & 15;

    float rA[2][8];
    auto ldgA = [&](int k0) {
#pragma unroll
        for (int p = 0; p < 2; p++) {
            float4 v0 = *(const float4*)(A + abase[p] + k0 + akq * 8);
            float4 v1 = *(const float4*)(A + abase[p] + k0 + akq * 8 + 4);
            rA[p][0] = v0.x; rA[p][1] = v0.y; rA[p][2] = v0.z; rA[p][3] = v0.w;
            rA[p][4] = v1.x; rA[p][5] = v1.y; rA[p][6] = v1.z; rA[p][7] = v1.w;
        }
    };
    auto stsA = [&](int st) {
#pragma unroll
        for (int p = 0; p < 2; p++) {
            uint32_t hi[4], lo[4];
            split8(rA[p], hi, lo);
            int off = st * PAST + (p * 64 + aml) * 72 + akq * 8;
            *(uint4*)(dyns + off)      = make_uint4(hi[0], hi[1], hi[2], hi[3]);
            *(uint4*)(dyns + off + 32) = make_uint4(lo[0], lo[1], lo[2], lo[3]);
        }
    };
    auto cpB = [&](int k0, int st) {
        uint32_t bbuf = sbase + (uint32_t)(PBBASE + st * PBST) * 2;
#pragma unroll
        for (int p = 0; p < 2; p++) {
            int row = p * 16 + bkr;
            cp16(bbuf + (uint32_t)(row * 264 + bnq * 8) * 2,
                 bhi + (size_t)(k0 + row) * N + n0 + bnq * 8);
            cp16(bbuf + (uint32_t)(row * 264 + 128 + bnq * 8) * 2,
                 blo + (size_t)(k0 + row) * N + n0 + bnq * 8);
        }
    };

    float acc[2][8][4];
#pragma unroll
    for (int i = 0; i < 2; i++)
#pragma unroll
        for (int j = 0; j < 8; j++)
#pragma unroll
            for (int q = 0; q < 4; q++) acc[i][j][q] = 0.f;

    const int nsteps = K / 32;
    ldgA(0); stsA(0);
    cpB(0, 0); CP_COMMIT();
    cpB(32, 1); CP_COMMIT();
    ldgA(32);

    for (int s = 0; s < nsteps; s++) {
        if (s == nsteps - 1) { CP_WAIT0(); } else { CP_WAIT1(); }
        if (s + 1 < nsteps) stsA((s + 1) % 3);
        __syncthreads();
        if (s + 2 < nsteps) {
            ldgA((s + 2) * 32);
            cpB((s + 2) * 32, (s + 2) % 3); CP_COMMIT();
        }
        const int st = s % 3;
#pragma unroll
        for (int kk = 0; kk < 2; kk++) {
            uint32_t a[2][2][4];
            const int ar_ = (lane & 7) + ((lane >> 3) & 1) * 8;
            const int ac_ = kk * 16 + ((lane >> 4) << 3);
#pragma unroll
            for (int hl = 0; hl < 2; hl++)
#pragma unroll
                for (int mi = 0; mi < 2; mi++) {
                    int ar = wm * 32 + mi * 16 + ar_;
                    ldsm_x4(a[hl][mi],
                            sbase + (uint32_t)(st * PAST + ar * 72 + hl * 32 + ac_) * 2);
                }
#pragma unroll
            for (int ng = 0; ng < 4; ng++) {
                uint32_t bh[4], bl[4];
                int br = kk * 16 + (lane & 7) + ((lane >> 3) & 1) * 8;
                int bc = wn * 64 + ng * 16 + ((lane >> 4) << 3);
                ldsm_x4t(bh, sbase + (uint32_t)(PBBASE + st * PBST + br * 264 + bc) * 2);
                ldsm_x4t(bl, sbase + (uint32_t)(PBBASE + st * PBST + br * 264 + 128 + bc) * 2);
#pragma unroll
                for (int n2 = 0; n2 < 2; n2++) {
                    int ni = ng * 2 + n2;
#pragma unroll
                    for (int mi = 0; mi < 2; mi++) {
                        mma16816(acc[mi][ni], a[0][mi], bh[n2 * 2], bh[n2 * 2 + 1]);
                        mma16816(acc[mi][ni], a[0][mi], bl[n2 * 2], bl[n2 * 2 + 1]);
                        mma16816(acc[mi][ni], a[1][mi], bh[n2 * 2], bh[n2 * 2 + 1]);
                    }
                }
            }
        }
    }

    const int rbase = m0 + wm * 32 + (lane >> 2);
#pragma unroll
    for (int mi = 0; mi < 2; mi++)
#pragma unroll
        for (int ni = 0; ni < 8; ni++) {
            const int col = n0 + wn * 64 + ni * 8 + (lane & 3) * 2;
            float bv0 = bs[col], bv1 = bs[col + 1];
#pragma unroll
            for (int h = 0; h < 2; h++) {
                int r = rbase + mi * 16 + h * 8;
                if (r >= M) continue;
                float v0 = acc[mi][ni][h * 2 + 0] + bv0;
                float v1 = acc[mi][ni][h * 2 + 1] + bv1;
                if (splitOut) {
                    size_t orow = remap ? (size_t)(r / 100) * 128 + (r % 100) : (size_t)r;
                    bf16 h0 = __float2bfloat16(v0), h1 = __float2bfloat16(v1);
                    __nv_bfloat162 hv; hv.x = h0; hv.y = h1;
                    *(uint32_t*)(Chi + orow * 256 + col) = *(uint32_t*)&hv;
                    *(uint32_t*)(Clo + orow * 256 + col) =
                        pack2(v0 - __bfloat162float(h0), v1 - __bfloat162float(h1));
                } else {
                    float2 t; t.x = v0; t.y = v1;
                    *(float2*)(Cf + (size_t)r * N + col) = t;
                }
            }
        }
}

// =====================================================================
// S GEMM (proven R12): interleaved hi/lo rows, 3-stage single-sync, 2 CTAs/SM.
// =====================================================================
#define SAST 9216
#define SBBASE2 (3 * SAST)
#define S_SMEM (6 * SAST * 2)     // 110592 B
__global__ __launch_bounds__(256, 2) void s_mma_k(
    const bf16* __restrict__ Ahi, const bf16* __restrict__ Alo,
    const bf16* __restrict__ Bhi, const bf16* __restrict__ Blo,
    float* __restrict__ C, const int M, const int N, const int K)
{
    extern __shared__ bf16 dyns[];
    const uint32_t sbase = (uint32_t)__cvta_generic_to_shared(dyns);

    const int tid = threadIdx.x, lane = tid & 31, w8 = tid >> 5;
    const int wm = w8 & 3, wn = w8 >> 2;
    const int m0 = blockIdx.y * 128, n0 = blockIdx.x * 128;

    const int akq = tid & 3, aml = tid >> 2;
    size_t abase[2], bnbase[2];
#pragma unroll
    for (int p = 0; p < 2; p++) {
        int m = m0 + p * 64 + aml;
        if (m >= M) m = M - 1;
        abase[p] = (size_t)m * K;
        bnbase[p] = (size_t)(n0 + p * 64 + aml) * K;
    }

    auto prefetch = [&](int k0, int st) {
        uint32_t abuf = sbase + (uint32_t)(st * SAST) * 2;
        uint32_t bbuf = sbase + (uint32_t)(SBBASE2 + st * SAST) * 2;
#pragma unroll
        for (int p = 0; p < 2; p++) {
            uint32_t off = (uint32_t)((p * 64 + aml) * 72 + akq * 8) * 2;
            cp16(abuf + off,      Ahi + abase[p] + k0 + akq * 8);
            cp16(abuf + off + 64, Alo + abase[p] + k0 + akq * 8);
            cp16(bbuf + off,      Bhi + bnbase[p] + k0 + akq * 8);
            cp16(bbuf + off + 64, Blo + bnbase[p] + k0 + akq * 8);
        }
    };

    float acc[2][8][4];
#pragma unroll
    for (int i = 0; i < 2; i++)
#pragma unroll
        for (int j = 0; j < 8; j++)
#pragma unroll
            for (int q = 0; q < 4; q++) acc[i][j][q] = 0.f;

    const int nsteps = K / 32;
    prefetch(0, 0); CP_COMMIT();
    prefetch(32, 1); CP_COMMIT();

    for (int s = 0; s < nsteps; s++) {
        if (s == nsteps - 1) { CP_WAIT0(); } else { CP_WAIT1(); }
        __syncthreads();
        if (s + 2 < nsteps) { prefetch((s + 2) * 32, (s + 2) % 3); CP_COMMIT(); }
        const int st = s % 3;
#pragma unroll
        for (int kk = 0; kk < 2; kk++) {
            uint32_t a[2][2][4];
            const int ar_ = (lane & 7) + ((lane >> 3) & 1) * 8;
            const int ac_ = kk * 16 + ((lane >> 4) << 3);
#pragma unroll
            for (int hl = 0; hl < 2; hl++)
#pragma unroll
                for (int mi = 0; mi < 2; mi++) {
                    int ar = wm * 32 + mi * 16 + ar_;
                    ldsm_x4(a[hl][mi],
                            sbase + (uint32_t)(st * SAST + ar * 72 + hl * 32 + ac_) * 2);
                }
#pragma unroll
            for (int ng = 0; ng < 4; ng++) {
                uint32_t bh[4], bl[4];
                int br = wn * 64 + ng * 16 + (lane & 7) + ((lane >> 4) << 3);
                int bc = kk * 16 + ((lane >> 3) & 1) * 8;
                ldsm_x4(bh, sbase + (uint32_t)(SBBASE2 + st * SAST + br * 72 + bc) * 2);
                ldsm_x4(bl, sbase + (uint32_t)(SBBASE2 + st * SAST + br * 72 + 32 + bc) * 2);
#pragma unroll
                for (int n2 = 0; n2 < 2; n2++) {
                    int ni = ng * 2 + n2;
#pragma unroll
                    for (int mi = 0; mi < 2; mi++) {
                        mma16816(acc[mi][ni], a[0][mi], bh[n2 * 2], bh[n2 * 2 + 1]);
                        mma16816(acc[mi][ni], a[0][mi], bl[n2 * 2], bl[n2 * 2 + 1]);
                        mma16816(acc[mi][ni], a[1][mi], bh[n2 * 2], bh[n2 * 2 + 1]);
                    }
                }
            }
        }
    }

    const int rbase = m0 + wm * 32 + (lane >> 2);
#pragma unroll
    for (int mi = 0; mi < 2; mi++)
#pragma unroll
        for (int ni = 0; ni < 8; ni++) {
            const int col = n0 + wn * 64 + ni * 8 + (lane & 3) * 2;
#pragma unroll
            for (int h = 0; h < 2; h++) {
                int r = rbase + mi * 16 + h * 8;
                if (r >= M) continue;
                float2 t;
                t.x = acc[mi][ni][h * 2 + 0] * 0.0625f;
                t.y = acc[mi][ni][h * 2 + 1] * 0.0625f;
                *(float2*)(C + (size_t)r * N + col) = t;
            }
        }
}

// =====================================================================
// Fused softmax + AV + logits (proven R12).
// =====================================================================
#define AV_PLO (128 * 136)
#define AV_BS  (2 * 128 * 136)
#define AV_BST (32 * 264)
#define AV_SMEM ((AV_BS + 6 * AV_BST) * 2)   // 171008 B
__global__ __launch_bounds__(512) void av_fused_k(
    const float* __restrict__ S, const bf16* __restrict__ Vhi, const bf16* __restrict__ Vlo,
    const float* __restrict__ Vw,
    float* __restrict__ att, float* __restrict__ avo)
{
    extern __shared__ bf16 dyns[];
    const uint32_t sbase = (uint32_t)__cvta_generic_to_shared(dyns);

    const int tid = threadIdx.x, lane = tid & 31, w16 = tid >> 5;
    const int wm = w16 & 3, wn = w16 >> 2;
    const int m0 = blockIdx.x * 128;
    const int bb = blockIdx.y;
    const int M = Bw * Tw;

    auto cpB = [&](int k0, int st) {
#pragma unroll
        for (int hl = 0; hl < 2; hl++) {
            const bf16* bs = hl ? Vlo : Vhi;
            uint32_t bbuf = sbase + (uint32_t)(AV_BS + (st * 2 + hl) * AV_BST) * 2;
#pragma unroll
            for (int p = 0; p < 2; p++) {
                int idx = tid + p * 512;
                int row = idx >> 5, ch = idx & 31;
                cp16(bbuf + (uint32_t)(row * 264 + ch * 8) * 2,
                     bs + ((size_t)bb * 128 + k0 + row) * 256 + ch * 8);
            }
        }
    };

    cpB(0, 0); CP_COMMIT();
    cpB(32, 1); CP_COMMIT();

    for (int i = w16; i < 128; i += 16) {
        int m = m0 + i;
        int mc = m < M ? m : M - 1;
        int w_ = mc / 30, t_ = mc - w_ * 30;
        const float* src = S + (size_t)(w_ * 30 + t_) * (Bo * To) + bb * 100;
        float4 v = make_float4(-1e30f, -1e30f, -1e30f, -1e30f);
        if (lane < 25) v = *(const float4*)(src + lane * 4);

        float mx = fmaxf(fmaxf(v.x, v.y), fmaxf(v.z, v.w));
#pragma unroll
        for (int off = 16; off; off >>= 1) mx = fmaxf(mx, __shfl_xor_sync(0xffffffffu, mx, off));
        float4 e;
        e.x = __expf(v.x - mx); e.y = __expf(v.y - mx);
        e.z = __expf(v.z - mx); e.w = __expf(v.w - mx);
        float sm = e.x + e.y + e.z + e.w;
#pragma unroll
        for (int off = 16; off; off >>= 1) sm += __shfl_xor_sync(0xffffffffu, sm, off);
        const float inv = 1.f / sm;

        const int base = i * 136 + lane * 4;
        if (lane < 25) {
            float r0 = e.x * inv, r1 = e.y * inv, r2 = e.z * inv, r3 = e.w * inv;
            if (m < M) {
                float* dst = att + ((size_t)(w_ * 96 + bb) * 30 + t_) * 100 + lane * 4;
                dst[0] = r0; dst[1] = r1; dst[2] = r2; dst[3] = r3;
            }
            bf16 h0 = __float2bfloat16(r0), h1 = __float2bfloat16(r1);
            __nv_bfloat162 hv; hv.x = h0; hv.y = h1;
            *(uint32_t*)(dyns + base) = *(uint32_t*)&hv;
            *(uint32_t*)(dyns + AV_PLO + base) =
                pack2(r0 - __bfloat162float(h0), r1 - __bfloat162float(h1));
            h0 = __float2bfloat16(r2); h1 = __float2bfloat16(r3);
            hv.x = h0; hv.y = h1;
            *(uint32_t*)(dyns + base + 2) = *(uint32_t*)&hv;
            *(uint32_t*)(dyns + AV_PLO + base + 2) =
                pack2(r2 - __bfloat162float(h0), r3 - __bfloat162float(h1));
        } else {
            *(uint32_t*)(dyns + base) = 0u;
            *(uint32_t*)(dyns + base + 2) = 0u;
            *(uint32_t*)(dyns + AV_PLO + base) = 0u;
            *(uint32_t*)(dyns + AV_PLO + base + 2) = 0u;
        }
    }
    CP_WAIT1();
    __syncthreads();

    float acc[2][8][4];
#pragma unroll
    for (int i = 0; i < 2; i++)
#pragma unroll
        for (int j = 0; j < 8; j++)
#pragma unroll
            for (int q = 0; q < 4; q++) acc[i][j][q] = 0.f;

#pragma unroll
    for (int s = 0; s < 4; s++) {
        if (s > 0) {
            if (s == 3) { CP_WAIT0(); } else { CP_WAIT1(); }
            __syncthreads();
        }
        if (s + 2 < 4) { cpB((s + 2) * 32, (s + 2) % 3); CP_COMMIT(); }
        const int st = s % 3;
#pragma unroll
        for (int kk = 0; kk < 2; kk++) {
            if (s == 3 && kk == 1) break;   // P cols 112..127 are all zero
            uint32_t a[2][2][4];
            const int ar_ = (lane & 7) + ((lane >> 3) & 1) * 8;
            const int ac_ = s * 32 + kk * 16 + ((lane >> 4) << 3);
#pragma unroll
            for (int hl = 0; hl < 2; hl++)
#pragma unroll
                for (int mi = 0; mi < 2; mi++) {
                    int ar = wm * 32 + mi * 16 + ar_;
                    ldsm_x4(a[hl][mi], sbase + (uint32_t)(hl * AV_PLO + ar * 136 + ac_) * 2);
                }
#pragma unroll
            for (int ng = 0; ng < 4; ng++) {
                uint32_t bh[4], bl[4];
                int br = kk * 16 + (lane & 7) + ((lane >> 3) & 1) * 8;
                int bc = wn * 64 + ng * 16 + ((lane >> 4) << 3);
                ldsm_x4t(bh, sbase + (uint32_t)(AV_BS + (st * 2 + 0) * AV_BST + br * 264 + bc) * 2);
                ldsm_x4t(bl, sbase + (uint32_t)(AV_BS + (st * 2 + 1) * AV_BST + br * 264 + bc) * 2);
#pragma unroll
                for (int n2 = 0; n2 < 2; n2++) {
                    int ni = ng * 2 + n2;
#pragma unroll
                    for (int mi = 0; mi < 2; mi++) {
                        mma16816(acc[mi][ni], a[0][mi], bh[n2 * 2], bh[n2 * 2 + 1]);
                        mma16816(acc[mi][ni], a[0][mi], bl[n2 * 2], bl[n2 * 2 + 1]);
                        mma16816(acc[mi][ni], a[1][mi], bh[n2 * 2], bh[n2 * 2 + 1]);
                    }
                }
            }
        }
    }

    const int rbase = m0 + wm * 32 + (lane >> 2);
#pragma unroll
    for (int mi = 0; mi < 2; mi++)
#pragma unroll
        for (int h = 0; h < 2; h++) {
            int r = rbase + mi * 16 + h * 8;
            bool ok = (r < M);
            int rc = ok ? r : M - 1;
            int w_ = rc / 30, t_ = rc - w_ * 30;
            float* prow = avo + ((size_t)(w_ * 96 + bb) * 30 + t_) * 256;
            const float* vwrow = Vw + (size_t)(w_ * 30 + t_) * 256;
            float s = 0.f;
#pragma unroll
            for (int ni = 0; ni < 8; ni++) {
                const int col = wn * 64 + ni * 8 + (lane & 3) * 2;
                float v0 = acc[mi][ni][h * 2 + 0];
                float v1 = acc[mi][ni][h * 2 + 1];
                if (ok) { prow[col] = v0; prow[col + 1] = v1; }
                float2 vw2 = *(const float2*)(vwrow + col);
                s += v0 * vw2.x + v1 * vw2.y;
            }
            s += __shfl_xor_sync(0xffffffffu, s, 1);
            s += __shfl_xor_sync(0xffffffffu, s, 2);
            if (ok && (lane & 3) == 0)
                atomicAdd(&logits_g[(size_t)(w_ * 96 + bb) * 30 + t_], s);
        }
}

// ---------------- loss ----------------
__global__ __launch_bounds__(256) void loss_terms_k(const float* __restrict__ mask)
{
    const int idx = blockIdx.x * 8 + (threadIdx.x >> 5);
    const int w = idx / Tw, t = idx % Tw;
    const int lane = threadIdx.x & 31;

    float m = -1e30f;
    for (int b = lane; b < Bo; b += 32)
        m = fmaxf(m, logits_g[((size_t)w * Bo + b) * Tw + t]);
#pragma unroll
    for (int off = 16; off; off >>= 1) m = fmaxf(m, __shfl_xor_sync(0xffffffffu, m, off));

    float s = 0.f;
    for (int b = lane; b < Bo; b += 32)
        s += __expf(logits_g[((size_t)w * Bo + b) * Tw + t] - m);
#pragma unroll
    for (int off = 16; off; off >>= 1) s += __shfl_xor_sync(0xffffffffu, s, off);
    float lse = m + __logf(s);

    float nm = (lane < Tw) ? (1.f - mask[w * Tw + lane]) : 0.f;
#pragma unroll
    for (int off = 16; off; off >>= 1) nm += __shfl_xor_sync(0xffffffffu, nm, off);

    if (lane == 0) {
        float diag = logits_g[((size_t)w * Bo + w) * Tw + t];
        terms_g[w * Tw + t] = (1.f - mask[w * Tw + t]) * (diag - lse) / (nm + 1e-6f);
    }
}

__global__ __launch_bounds__(256) void loss_final_k(float* __restrict__ out)
{
    __shared__ float sh[256];
    float s = 0.f;
    for (int i = threadIdx.x; i < Bw * Tw; i += 256) s += terms_g[i];
    sh[threadIdx.x] = s;
    __syncthreads();
#pragma unroll
    for (int off = 128; off; off >>= 1) {
        if (threadIdx.x < off) sh[threadIdx.x] += sh[threadIdx.x + off];
        __syncthreads();
    }
    if (threadIdx.x == 0) out[0] = -sh[0] / (float)Bw;
}

// ---------------- launch ----------------
static inline void* sym(const void* s) { void* p; cudaGetSymbolAddress(&p, s); return p; }

extern "C" void kernel_launch(void* const* d_in, const int* in_sizes, int n_in,
                              void* d_out, int out_size)
{
    const float* o    = (const float*)d_in[0];
    const float* u    = (const float*)d_in[1];
    const float* w    = (const float*)d_in[2];
    const float* mask = (const float*)d_in[3];
    const float* Wku  = (const float*)d_in[4];
    const float* bku  = (const float*)d_in[5];
    const float* Wkw  = (const float*)d_in[6];
    const float* bkw  = (const float*)d_in[7];
    const float* Wfo  = (const float*)d_in[8];
    const float* bfo  = (const float*)d_in[9];
    const float* Wfw  = (const float*)d_in[10];
    const float* bfw  = (const float*)d_in[11];

    float* out = (float*)d_out;
    float* att_out = out + 1;
    float* avo_out = out + 1 + (size_t)Bw * Bo * Tw * To;

    bf16 *Kuhi = (bf16*)sym(Kuhi_g), *Kulo = (bf16*)sym(Kulo_g);
    bf16 *Kwhi = (bf16*)sym(Kwhi_g), *Kwlo = (bf16*)sym(Kwlo_g);
    bf16 *Vohi = (bf16*)sym(Vohi_g), *Volo = (bf16*)sym(Volo_g);
    float *pVw = (float*)sym(Vw_g), *pS = (float*)sym(S_g);

    cudaFuncSetAttribute(proj_grp_k, cudaFuncAttributeMaxDynamicSharedMemorySize, PROJ_SMEM);
    cudaFuncSetAttribute(s_mma_k,    cudaFuncAttributeMaxDynamicSharedMemorySize, S_SMEM);
    cudaFuncSetAttribute(av_fused_k, cudaFuncAttributeMaxDynamicSharedMemorySize, AV_SMEM);

    // side stream + fork/join events
    static cudaStream_t s1 = nullptr;
    static cudaEvent_t evFork = nullptr, evJoin = nullptr;
    if (s1 == nullptr) {
        cudaStreamCreateWithFlags(&s1, cudaStreamNonBlocking);
        cudaEventCreateWithFlags(&evFork, cudaEventDisableTiming);
        cudaEventCreateWithFlags(&evJoin, cudaEventDisableTiming);
    }

    // stream 0: weight splits
    split_all_k<<<N4 / 256 + 1, 256>>>(Wku, Wkw, Wfo, Wfw);
    cudaEventRecord(evFork, 0);
    cudaStreamWaitEvent(s1, evFork, 0);

    // stream 1 (off critical path): zero logits + Vo/Vw projections
    zero_logits_k<<<(Bw * Bo * Tw) / 1024, 1024, 0, s1>>>();
    proj_grp_k<<<196, 256, PROJ_SMEM, s1>>>(u, o, w, bku, bkw, bfo, bfw, 1);
    cudaEventRecord(evJoin, s1);

    // stream 0 (critical path): Ku/Kw projections -> S
    proj_grp_k<<<196, 256, PROJ_SMEM>>>(u, o, w, bku, bkw, bfo, bfw, 0);
    s_mma_k<<<dim3(75, 23), 256, S_SMEM>>>(Kwhi, Kwlo, Kuhi, Kulo, pS, Bw * Tw, Bo * To, Dk);

    // join: av needs Vo/Vw/logits(zeroed) from stream 1
    cudaStreamWaitEvent(0, evJoin, 0);
    av_fused_k<<<dim3(23, 96), 512, AV_SMEM>>>(pS, Vohi, Volo, pVw, att_out, avo_out);

    // loss
    loss_terms_k<<<(Bw * Tw) / 8, 256>>>(mask);
    loss_final_k<<<1, 256>>>(out);
}

// round 15
// speedup vs baseline: 1.0192x; 1.0192x over previous
#include <cuda_runtime.h>
#include <cuda_bf16.h>
#include <cstdint>

#define Bo 96
#define To 100
#define Do 1024
#define Bw 96
#define Tw 30
#define Dw 768
#define Du 2048
#define Dk 256
#define Dv 256

typedef __nv_bfloat16 bf16;

// ---------------- scratch ----------------
__device__ __align__(256) bf16 Wkuhi_g[Du * Dk], Wkulo_g[Du * Dk];
__device__ __align__(256) bf16 Wkwhi_g[Dw * Dk], Wkwlo_g[Dw * Dk];
__device__ __align__(256) bf16 Wfohi_g[Do * Dv], Wfolo_g[Do * Dv];
__device__ __align__(256) bf16 Wfwhi_g[Dw * Dv], Wfwlo_g[Dw * Dv];
__device__ __align__(256) bf16 Kuhi_g[(size_t)Bo * To * Dk], Kulo_g[(size_t)Bo * To * Dk];
__device__ __align__(256) bf16 Kwhi_g[(size_t)Bw * Tw * Dk], Kwlo_g[(size_t)Bw * Tw * Dk];
__device__ __align__(256) bf16 Vohi_g[(size_t)Bo * 128 * Dv], Volo_g[(size_t)Bo * 128 * Dv];
__device__ __align__(256) float Vw_g[(size_t)Bw * Tw * Dv];
__device__ __align__(256) float S_g[(size_t)Bw * Tw * Bo * To];
__device__ __align__(256) float logits_g[(size_t)Bw * Bo * Tw];
__device__ __align__(256) float terms_g[(size_t)Bw * Tw];

// ---------------- helpers ----------------
__device__ __forceinline__ void ldsm_x4(uint32_t* r, uint32_t addr) {
    asm volatile("ldmatrix.sync.aligned.m8n8.x4.shared.b16 {%0,%1,%2,%3},[%4];"
                 : "=r"(r[0]), "=r"(r[1]), "=r"(r[2]), "=r"(r[3]) : "r"(addr));
}
__device__ __forceinline__ void ldsm_x4t(uint32_t* r, uint32_t addr) {
    asm volatile("ldmatrix.sync.aligned.m8n8.x4.trans.shared.b16 {%0,%1,%2,%3},[%4];"
                 : "=r"(r[0]), "=r"(r[1]), "=r"(r[2]), "=r"(r[3]) : "r"(addr));
}
__device__ __forceinline__ void mma16816(float* c, const uint32_t* a, uint32_t b0, uint32_t b1) {
    asm volatile("mma.sync.aligned.m16n8k16.row.col.f32.bf16.bf16.f32 "
                 "{%0,%1,%2,%3},{%4,%5,%6,%7},{%8,%9},{%0,%1,%2,%3};"
                 : "+f"(c[0]), "+f"(c[1]), "+f"(c[2]), "+f"(c[3])
                 : "r"(a[0]), "r"(a[1]), "r"(a[2]), "r"(a[3]), "r"(b0), "r"(b1));
}
__device__ __forceinline__ void cp16(uint32_t dst, const void* src) {
    asm volatile("cp.async.cg.shared.global [%0],[%1],16;" :: "r"(dst), "l"(src));
}
#define CP_COMMIT() asm volatile("cp.async.commit_group;")
#define CP_WAIT1()  asm volatile("cp.async.wait_group 1;")
#define CP_WAIT0()  asm volatile("cp.async.wait_group 0;")

__device__ __forceinline__ uint32_t pack2(float a, float b) {
    __nv_bfloat162 v = __floats2bfloat162_rn(a, b);
    return *(uint32_t*)&v;
}
__device__ __forceinline__ void split8(const float* f, uint32_t* hi, uint32_t* lo) {
#pragma unroll
    for (int j = 0; j < 4; j++) {
        bf16 h0 = __float2bfloat16(f[2 * j]);
        bf16 h1 = __float2bfloat16(f[2 * j + 1]);
        __nv_bfloat162 hv; hv.x = h0; hv.y = h1;
        hi[j] = *(uint32_t*)&hv;
        lo[j] = pack2(f[2 * j] - __bfloat162float(h0), f[2 * j + 1] - __bfloat162float(h1));
    }
}

// ---------------- merged weight split ----------------
#define N1 (Du * Dk / 4)
#define N2 (N1 + Dw * Dk / 4)
#define N3 (N2 + Do * Dv / 4)
#define N4 (N3 + Dw * Dv / 4)
__global__ __launch_bounds__(256) void split_all_k(
    const float* __restrict__ Wku, const float* __restrict__ Wkw,
    const float* __restrict__ Wfo, const float* __restrict__ Wfw)
{
    int i = blockIdx.x * 256 + threadIdx.x;
    if (i >= N4) return;
    const float* src; bf16 *hi, *lo; int j;
    if (i < N1)      { src = Wku; hi = Wkuhi_g; lo = Wkulo_g; j = i; }
    else if (i < N2) { src = Wkw; hi = Wkwhi_g; lo = Wkwlo_g; j = i - N1; }
    else if (i < N3) { src = Wfo; hi = Wfohi_g; lo = Wfolo_g; j = i - N2; }
    else             { src = Wfw; hi = Wfwhi_g; lo = Wfwlo_g; j = i - N3; }
    float4 v = ((const float4*)src)[j];
    float f[4] = {v.x, v.y, v.z, v.w};
    uint32_t h[2], l[2];
#pragma unroll
    for (int q = 0; q < 2; q++) {
        bf16 h0 = __float2bfloat16(f[2 * q]), h1 = __float2bfloat16(f[2 * q + 1]);
        __nv_bfloat162 hv; hv.x = h0; hv.y = h1;
        h[q] = *(uint32_t*)&hv;
        l[q] = pack2(f[2 * q] - __bfloat162float(h0), f[2 * q + 1] - __bfloat162float(h1));
    }
    ((uint32_t*)hi)[j * 2] = h[0]; ((uint32_t*)hi)[j * 2 + 1] = h[1];
    ((uint32_t*)lo)[j * 2] = l[0]; ((uint32_t*)lo)[j * 2 + 1] = l[1];
}

__global__ __launch_bounds__(1024) void zero_logits_k() {
    logits_g[blockIdx.x * 1024 + threadIdx.x] = 0.f;
}

// =====================================================================
// Projection GEMM, grouped (R13 proven layout). 3-stage single-sync.
// grp 0: Ku (K=2048) / Kw (K=768).  grp 1: Vo (K=1024, remap) / Vw (fp32).
// =====================================================================
#define PAS 5120
#define PBS 4352
#define PBBASE (6 * PAS)
#define PROJ_SMEM ((6 * PAS + 6 * PBS) * 2)   // 113664 B

__global__ __launch_bounds__(256, 2) void proj_grp_k(
    const float* __restrict__ u, const float* __restrict__ o, const float* __restrict__ w,
    const float* __restrict__ bku, const float* __restrict__ bkw,
    const float* __restrict__ bfo, const float* __restrict__ bfw,
    const int grp)
{
    extern __shared__ bf16 dyns[];
    const uint32_t sbase = (uint32_t)__cvta_generic_to_shared(dyns);
    const int N = 256;
    const int tid = threadIdx.x, lane = tid & 31, w8 = tid >> 5;
    const int wm = w8 & 3, wn = w8 >> 2;
    const int bid = blockIdx.x;

    const float* A; const bf16 *bhi, *blo; const float* bs;
    bf16 *Chi = nullptr, *Clo = nullptr; float* Cf = nullptr;
    int M, K, n0, m0, remap = 0; bool splitOut;

    if (bid < 150) {
        n0 = (bid & 1) * 128; m0 = (bid >> 1) * 128; M = Bo * To;
        if (grp == 0) {
            A = u; K = Du; bhi = Wkuhi_g; blo = Wkulo_g; bs = bku;
            Chi = Kuhi_g; Clo = Kulo_g; splitOut = true;
        } else {
            A = o; K = Do; bhi = Wfohi_g; blo = Wfolo_g; bs = bfo;
            Chi = Vohi_g; Clo = Volo_g; splitOut = true; remap = 1;
        }
    } else {
        int b2 = bid - 150;
        n0 = (b2 & 1) * 128; m0 = (b2 >> 1) * 128;
        A = w; K = Dw; M = Bw * Tw;
        if (grp == 0) {
            bhi = Wkwhi_g; blo = Wkwlo_g; bs = bkw;
            Chi = Kwhi_g; Clo = Kwlo_g; splitOut = true;
        } else {
            bhi = Wfwhi_g; blo = Wfwlo_g; bs = bfw; Cf = Vw_g; splitOut = false;
        }
    }

    const int akq = tid & 3, aml = tid >> 2;
    size_t abase[2];
#pragma unroll
    for (int p = 0; p < 2; p++) {
        int m = m0 + p * 64 + aml;
        if (m >= M) m = M - 1;
        abase[p] = (size_t)m * K;
    }
    const int bkr = tid >> 4, bnq = tid & 15;

    float rA[2][8];
    auto ldgA = [&](int k0) {
#pragma unroll
        for (int p = 0; p < 2; p++) {
            float4 v0 = *(const float4*)(A + abase[p] + k0 + akq * 8);
            float4 v1 = *(const float4*)(A + abase[p] + k0 + akq * 8 + 4);
            rA[p][0] = v0.x; rA[p][1] = v0.y; rA[p][2] = v0.z; rA[p][3] = v0.w;
            rA[p][4] = v1.x; rA[p][5] = v1.y; rA[p][6] = v1.z; rA[p][7] = v1.w;
        }
    };
    auto stsA = [&](int st) {
#pragma unroll
        for (int p = 0; p < 2; p++) {
            uint32_t hi[4], lo[4];
            split8(rA[p], hi, lo);
            int off = (p * 64 + aml) * 40 + akq * 8;
            *(uint4*)(dyns + (st * 2 + 0) * PAS + off) = make_uint4(hi[0], hi[1], hi[2], hi[3]);
            *(uint4*)(dyns + (st * 2 + 1) * PAS + off) = make_uint4(lo[0], lo[1], lo[2], lo[3]);
        }
    };
    auto cpB = [&](int k0, int st) {
#pragma unroll
        for (int hl = 0; hl < 2; hl++) {
            const bf16* bsrc = hl ? blo : bhi;
            uint32_t bbuf = sbase + (uint32_t)(PBBASE + (st * 2 + hl) * PBS) * 2;
#pragma unroll
            for (int p = 0; p < 2; p++) {
                int row = p * 16 + bkr;
                cp16(bbuf + (uint32_t)(row * 136 + bnq * 8) * 2,
                     bsrc + (size_t)(k0 + row) * N + n0 + bnq * 8);
            }
        }
    };

    float acc[2][8][4];
#pragma unroll
    for (int i = 0; i < 2; i++)
#pragma unroll
        for (int j = 0; j < 8; j++)
#pragma unroll
            for (int q = 0; q < 4; q++) acc[i][j][q] = 0.f;

    const int nsteps = K / 32;
    ldgA(0); stsA(0);
    cpB(0, 0); CP_COMMIT();
    cpB(32, 1); CP_COMMIT();
    ldgA(32);

    for (int s = 0; s < nsteps; s++) {
        if (s == nsteps - 1) { CP_WAIT0(); } else { CP_WAIT1(); }
        if (s + 1 < nsteps) stsA((s + 1) % 3);
        __syncthreads();
        if (s + 2 < nsteps) {
            ldgA((s + 2) * 32);
            cpB((s + 2) * 32, (s + 2) % 3); CP_COMMIT();
        }
        const int st = s % 3;
#pragma unroll
        for (int kk = 0; kk < 2; kk++) {
            uint32_t a[2][2][4];
            const int ar_ = (lane & 7) + ((lane >> 3) & 1) * 8;
            const int ac_ = kk * 16 + ((lane >> 4) << 3);
#pragma unroll
            for (int hl = 0; hl < 2; hl++)
#pragma unroll
                for (int mi = 0; mi < 2; mi++) {
                    int ar = wm * 32 + mi * 16 + ar_;
                    ldsm_x4(a[hl][mi], sbase + (uint32_t)((st * 2 + hl) * PAS + ar * 40 + ac_) * 2);
                }
#pragma unroll
            for (int ng = 0; ng < 4; ng++) {
                uint32_t bh[4], bl[4];
                int br = kk * 16 + (lane & 7) + ((lane >> 3) & 1) * 8;
                int bc = wn * 64 + ng * 16 + ((lane >> 4) << 3);
                ldsm_x4t(bh, sbase + (uint32_t)(PBBASE + (st * 2 + 0) * PBS + br * 136 + bc) * 2);
                ldsm_x4t(bl, sbase + (uint32_t)(PBBASE + (st * 2 + 1) * PBS + br * 136 + bc) * 2);
#pragma unroll
                for (int n2 = 0; n2 < 2; n2++) {
                    int ni = ng * 2 + n2;
#pragma unroll
                    for (int mi = 0; mi < 2; mi++) {
                        mma16816(acc[mi][ni], a[0][mi], bh[n2 * 2], bh[n2 * 2 + 1]);
                        mma16816(acc[mi][ni], a[0][mi], bl[n2 * 2], bl[n2 * 2 + 1]);
                        mma16816(acc[mi][ni], a[1][mi], bh[n2 * 2], bh[n2 * 2 + 1]);
                    }
                }
            }
        }
    }

    const int rbase = m0 + wm * 32 + (lane >> 2);
#pragma unroll
    for (int mi = 0; mi < 2; mi++)
#pragma unroll
        for (int ni = 0; ni < 8; ni++) {
            const int col = n0 + wn * 64 + ni * 8 + (lane & 3) * 2;
            float bv0 = bs[col], bv1 = bs[col + 1];
#pragma unroll
            for (int h = 0; h < 2; h++) {
                int r = rbase + mi * 16 + h * 8;
                if (r >= M) continue;
                float v0 = acc[mi][ni][h * 2 + 0] + bv0;
                float v1 = acc[mi][ni][h * 2 + 1] + bv1;
                if (splitOut) {
                    size_t orow = remap ? (size_t)(r / 100) * 128 + (r % 100) : (size_t)r;
                    bf16 h0 = __float2bfloat16(v0), h1 = __float2bfloat16(v1);
                    __nv_bfloat162 hv; hv.x = h0; hv.y = h1;
                    *(uint32_t*)(Chi + orow * 256 + col) = *(uint32_t*)&hv;
                    *(uint32_t*)(Clo + orow * 256 + col) =
                        pack2(v0 - __bfloat162float(h0), v1 - __bfloat162float(h1));
                } else {
                    float2 t; t.x = v0; t.y = v1;
                    *(float2*)(Cf + (size_t)r * N + col) = t;
                }
            }
        }
}

// =====================================================================
// S GEMM (proven R12) with y-band offset for pipelining.
// =====================================================================
#define SAST 9216
#define SBBASE2 (3 * SAST)
#define S_SMEM (6 * SAST * 2)
__global__ __launch_bounds__(256, 2) void s_mma_k(
    const bf16* __restrict__ Ahi, const bf16* __restrict__ Alo,
    const bf16* __restrict__ Bhi, const bf16* __restrict__ Blo,
    float* __restrict__ C, const int M, const int N, const int K, const int y0)
{
    extern __shared__ bf16 dyns[];
    const uint32_t sbase = (uint32_t)__cvta_generic_to_shared(dyns);

    const int tid = threadIdx.x, lane = tid & 31, w8 = tid >> 5;
    const int wm = w8 & 3, wn = w8 >> 2;
    const int m0 = (blockIdx.y + y0) * 128, n0 = blockIdx.x * 128;

    const int akq = tid & 3, aml = tid >> 2;
    size_t abase[2], bnbase[2];
#pragma unroll
    for (int p = 0; p < 2; p++) {
        int m = m0 + p * 64 + aml;
        if (m >= M) m = M - 1;
        abase[p] = (size_t)m * K;
        bnbase[p] = (size_t)(n0 + p * 64 + aml) * K;
    }

    auto prefetch = [&](int k0, int st) {
        uint32_t abuf = sbase + (uint32_t)(st * SAST) * 2;
        uint32_t bbuf = sbase + (uint32_t)(SBBASE2 + st * SAST) * 2;
#pragma unroll
        for (int p = 0; p < 2; p++) {
            uint32_t off = (uint32_t)((p * 64 + aml) * 72 + akq * 8) * 2;
            cp16(abuf + off,      Ahi + abase[p] + k0 + akq * 8);
            cp16(abuf + off + 64, Alo + abase[p] + k0 + akq * 8);
            cp16(bbuf + off,      Bhi + bnbase[p] + k0 + akq * 8);
            cp16(bbuf + off + 64, Blo + bnbase[p] + k0 + akq * 8);
        }
    };

    float acc[2][8][4];
#pragma unroll
    for (int i = 0; i < 2; i++)
#pragma unroll
        for (int j = 0; j < 8; j++)
#pragma unroll
            for (int q = 0; q < 4; q++) acc[i][j][q] = 0.f;

    const int nsteps = K / 32;
    prefetch(0, 0); CP_COMMIT();
    prefetch(32, 1); CP_COMMIT();

    for (int s = 0; s < nsteps; s++) {
        if (s == nsteps - 1) { CP_WAIT0(); } else { CP_WAIT1(); }
        __syncthreads();
        if (s + 2 < nsteps) { prefetch((s + 2) * 32, (s + 2) % 3); CP_COMMIT(); }
        const int st = s % 3;
#pragma unroll
        for (int kk = 0; kk < 2; kk++) {
            uint32_t a[2][2][4];
            const int ar_ = (lane & 7) + ((lane >> 3) & 1) * 8;
            const int ac_ = kk * 16 + ((lane >> 4) << 3);
#pragma unroll
            for (int hl = 0; hl < 2; hl++)
#pragma unroll
                for (int mi = 0; mi < 2; mi++) {
                    int ar = wm * 32 + mi * 16 + ar_;
                    ldsm_x4(a[hl][mi],
                            sbase + (uint32_t)(st * SAST + ar * 72 + hl * 32 + ac_) * 2);
                }
#pragma unroll
            for (int ng = 0; ng < 4; ng++) {
                uint32_t bh[4], bl[4];
                int br = wn * 64 + ng * 16 + (lane & 7) + ((lane >> 4) << 3);
                int bc = kk * 16 + ((lane >> 3) & 1) * 8;
                ldsm_x4(bh, sbase + (uint32_t)(SBBASE2 + st * SAST + br * 72 + bc) * 2);
                ldsm_x4(bl, sbase + (uint32_t)(SBBASE2 + st * SAST + br * 72 + 32 + bc) * 2);
#pragma unroll
                for (int n2 = 0; n2 < 2; n2++) {
                    int ni = ng * 2 + n2;
#pragma unroll
                    for (int mi = 0; mi < 2; mi++) {
                        mma16816(acc[mi][ni], a[0][mi], bh[n2 * 2], bh[n2 * 2 + 1]);
                        mma16816(acc[mi][ni], a[0][mi], bl[n2 * 2], bl[n2 * 2 + 1]);
                        mma16816(acc[mi][ni], a[1][mi], bh[n2 * 2], bh[n2 * 2 + 1]);
                    }
                }
            }
        }
    }

    const int rbase = m0 + wm * 32 + (lane >> 2);
#pragma unroll
    for (int mi = 0; mi < 2; mi++)
#pragma unroll
        for (int ni = 0; ni < 8; ni++) {
            const int col = n0 + wn * 64 + ni * 8 + (lane & 3) * 2;
#pragma unroll
            for (int h = 0; h < 2; h++) {
                int r = rbase + mi * 16 + h * 8;
                if (r >= M) continue;
                float2 t;
                t.x = acc[mi][ni][h * 2 + 0] * 0.0625f;
                t.y = acc[mi][ni][h * 2 + 1] * 0.0625f;
                *(float2*)(C + (size_t)r * N + col) = t;
            }
        }
}

// =====================================================================
// Fused softmax + AV + logits (proven R12) with x-band offset.
// =====================================================================
#define AV_PLO (128 * 136)
#define AV_BS  (2 * 128 * 136)
#define AV_BST (32 * 264)
#define AV_SMEM ((AV_BS + 6 * AV_BST) * 2)
__global__ __launch_bounds__(512) void av_fused_k(
    const float* __restrict__ S, const bf16* __restrict__ Vhi, const bf16* __restrict__ Vlo,
    const float* __restrict__ Vw,
    float* __restrict__ att, float* __restrict__ avo, const int x0)
{
    extern __shared__ bf16 dyns[];
    const uint32_t sbase = (uint32_t)__cvta_generic_to_shared(dyns);

    const int tid = threadIdx.x, lane = tid & 31, w16 = tid >> 5;
    const int wm = w16 & 3, wn = w16 >> 2;
    const int m0 = (blockIdx.x + x0) * 128;
    const int bb = blockIdx.y;
    const int M = Bw * Tw;

    auto cpB = [&](int k0, int st) {
#pragma unroll
        for (int hl = 0; hl < 2; hl++) {
            const bf16* bs = hl ? Vlo : Vhi;
            uint32_t bbuf = sbase + (uint32_t)(AV_BS + (st * 2 + hl) * AV_BST) * 2;
#pragma unroll
            for (int p = 0; p < 2; p++) {
                int idx = tid + p * 512;
                int row = idx >> 5, ch = idx & 31;
                cp16(bbuf + (uint32_t)(row * 264 + ch * 8) * 2,
                     bs + ((size_t)bb * 128 + k0 + row) * 256 + ch * 8);
            }
        }
    };

    cpB(0, 0); CP_COMMIT();
    cpB(32, 1); CP_COMMIT();

    for (int i = w16; i < 128; i += 16) {
        int m = m0 + i;
        int mc = m < M ? m : M - 1;
        int w_ = mc / 30, t_ = mc - w_ * 30;
        const float* src = S + (size_t)(w_ * 30 + t_) * (Bo * To) + bb * 100;
        float4 v = make_float4(-1e30f, -1e30f, -1e30f, -1e30f);
        if (lane < 25) v = *(const float4*)(src + lane * 4);

        float mx = fmaxf(fmaxf(v.x, v.y), fmaxf(v.z, v.w));
#pragma unroll
        for (int off = 16; off; off >>= 1) mx = fmaxf(mx, __shfl_xor_sync(0xffffffffu, mx, off));
        float4 e;
        e.x = __expf(v.x - mx); e.y = __expf(v.y - mx);
        e.z = __expf(v.z - mx); e.w = __expf(v.w - mx);
        float sm = e.x + e.y + e.z + e.w;
#pragma unroll
        for (int off = 16; off; off >>= 1) sm += __shfl_xor_sync(0xffffffffu, sm, off);
        const float inv = 1.f / sm;

        const int base = i * 136 + lane * 4;
        if (lane < 25) {
            float r0 = e.x * inv, r1 = e.y * inv, r2 = e.z * inv, r3 = e.w * inv;
            if (m < M) {
                float* dst = att + ((size_t)(w_ * 96 + bb) * 30 + t_) * 100 + lane * 4;
                dst[0] = r0; dst[1] = r1; dst[2] = r2; dst[3] = r3;
            }
            bf16 h0 = __float2bfloat16(r0), h1 = __float2bfloat16(r1);
            __nv_bfloat162 hv; hv.x = h0; hv.y = h1;
            *(uint32_t*)(dyns + base) = *(uint32_t*)&hv;
            *(uint32_t*)(dyns + AV_PLO + base) =
                pack2(r0 - __bfloat162float(h0), r1 - __bfloat162float(h1));
            h0 = __float2bfloat16(r2); h1 = __float2bfloat16(r3);
            hv.x = h0; hv.y = h1;
            *(uint32_t*)(dyns + base + 2) = *(uint32_t*)&hv;
            *(uint32_t*)(dyns + AV_PLO + base + 2) =
                pack2(r2 - __bfloat162float(h0), r3 - __bfloat162float(h1));
        } else {
            *(uint32_t*)(dyns + base) = 0u;
            *(uint32_t*)(dyns + base + 2) = 0u;
            *(uint32_t*)(dyns + AV_PLO + base) = 0u;
            *(uint32_t*)(dyns + AV_PLO + base + 2) = 0u;
        }
    }
    CP_WAIT1();
    __syncthreads();

    float acc[2][8][4];
#pragma unroll
    for (int i = 0; i < 2; i++)
#pragma unroll
        for (int j = 0; j < 8; j++)
#pragma unroll
            for (int q = 0; q < 4; q++) acc[i][j][q] = 0.f;

#pragma unroll
    for (int s = 0; s < 4; s++) {
        if (s > 0) {
            if (s == 3) { CP_WAIT0(); } else { CP_WAIT1(); }
            __syncthreads();
        }
        if (s + 2 < 4) { cpB((s + 2) * 32, (s + 2) % 3); CP_COMMIT(); }
        const int st = s % 3;
#pragma unroll
        for (int kk = 0; kk < 2; kk++) {
            if (s == 3 && kk == 1) break;   // P cols 112..127 are all zero
            uint32_t a[2][2][4];
            const int ar_ = (lane & 7) + ((lane >> 3) & 1) * 8;
            const int ac_ = s * 32 + kk * 16 + ((lane >> 4) << 3);
#pragma unroll
            for (int hl = 0; hl < 2; hl++)
#pragma unroll
                for (int mi = 0; mi < 2; mi++) {
                    int ar = wm * 32 + mi * 16 + ar_;
                    ldsm_x4(a[hl][mi], sbase + (uint32_t)(hl * AV_PLO + ar * 136 + ac_) * 2);
                }
#pragma unroll
            for (int ng = 0; ng < 4; ng++) {
                uint32_t bh[4], bl[4];
                int br = kk * 16 + (lane & 7) + ((lane >> 3) & 1) * 8;
                int bc = wn * 64 + ng * 16 + ((lane >> 4) << 3);
                ldsm_x4t(bh, sbase + (uint32_t)(AV_BS + (st * 2 + 0) * AV_BST + br * 264 + bc) * 2);
                ldsm_x4t(bl, sbase + (uint32_t)(AV_BS + (st * 2 + 1) * AV_BST + br * 264 + bc) * 2);
#pragma unroll
                for (int n2 = 0; n2 < 2; n2++) {
                    int ni = ng * 2 + n2;
#pragma unroll
                    for (int mi = 0; mi < 2; mi++) {
                        mma16816(acc[mi][ni], a[0][mi], bh[n2 * 2], bh[n2 * 2 + 1]);
                        mma16816(acc[mi][ni], a[0][mi], bl[n2 * 2], bl[n2 * 2 + 1]);
                        mma16816(acc[mi][ni], a[1][mi], bh[n2 * 2], bh[n2 * 2 + 1]);
                    }
                }
            }
        }
    }

    const int rbase = m0 + wm * 32 + (lane >> 2);
#pragma unroll
    for (int mi = 0; mi < 2; mi++)
#pragma unroll
        for (int h = 0; h < 2; h++) {
            int r = rbase + mi * 16 + h * 8;
            bool ok = (r < M);
            int rc = ok ? r : M - 1;
            int w_ = rc / 30, t_ = rc - w_ * 30;
            float* prow = avo + ((size_t)(w_ * 96 + bb) * 30 + t_) * 256;
            const float* vwrow = Vw + (size_t)(w_ * 30 + t_) * 256;
            float s = 0.f;
#pragma unroll
            for (int ni = 0; ni < 8; ni++) {
                const int col = wn * 64 + ni * 8 + (lane & 3) * 2;
                float v0 = acc[mi][ni][h * 2 + 0];
                float v1 = acc[mi][ni][h * 2 + 1];
                if (ok) { prow[col] = v0; prow[col + 1] = v1; }
                float2 vw2 = *(const float2*)(vwrow + col);
                s += v0 * vw2.x + v1 * vw2.y;
            }
            s += __shfl_xor_sync(0xffffffffu, s, 1);
            s += __shfl_xor_sync(0xffffffffu, s, 2);
            if (ok && (lane & 3) == 0)
                atomicAdd(&logits_g[(size_t)(w_ * 96 + bb) * 30 + t_], s);
        }
}

// ---------------- loss ----------------
__global__ __launch_bounds__(256) void loss_terms_k(const float* __restrict__ mask)
{
    const int idx = blockIdx.x * 8 + (threadIdx.x >> 5);
    const int w = idx / Tw, t = idx % Tw;
    const int lane = threadIdx.x & 31;

    float m = -1e30f;
    for (int b = lane; b < Bo; b += 32)
        m = fmaxf(m, logits_g[((size_t)w * Bo + b) * Tw + t]);
#pragma unroll
    for (int off = 16; off; off >>= 1) m = fmaxf(m, __shfl_xor_sync(0xffffffffu, m, off));

    float s = 0.f;
    for (int b = lane; b < Bo; b += 32)
        s += __expf(logits_g[((size_t)w * Bo + b) * Tw + t] - m);
#pragma unroll
    for (int off = 16; off; off >>= 1) s += __shfl_xor_sync(0xffffffffu, s, off);
    float lse = m + __logf(s);

    float nm = (lane < Tw) ? (1.f - mask[w * Tw + lane]) : 0.f;
#pragma unroll
    for (int off = 16; off; off >>= 1) nm += __shfl_xor_sync(0xffffffffu, nm, off);

    if (lane == 0) {
        float diag = logits_g[((size_t)w * Bo + w) * Tw + t];
        terms_g[w * Tw + t] = (1.f - mask[w * Tw + t]) * (diag - lse) / (nm + 1e-6f);
    }
}

__global__ __launch_bounds__(256) void loss_final_k(float* __restrict__ out)
{
    __shared__ float sh[256];
    float s = 0.f;
    for (int i = threadIdx.x; i < Bw * Tw; i += 256) s += terms_g[i];
    sh[threadIdx.x] = s;
    __syncthreads();
#pragma unroll
    for (int off = 128; off; off >>= 1) {
        if (threadIdx.x < off) sh[threadIdx.x] += sh[threadIdx.x + off];
        __syncthreads();
    }
    if (threadIdx.x == 0) out[0] = -sh[0] / (float)Bw;
}

// ---------------- launch ----------------
static inline void* sym(const void* s) { void* p; cudaGetSymbolAddress(&p, s); return p; }

extern "C" void kernel_launch(void* const* d_in, const int* in_sizes, int n_in,
                              void* d_out, int out_size)
{
    const float* o    = (const float*)d_in[0];
    const float* u    = (const float*)d_in[1];
    const float* w    = (const float*)d_in[2];
    const float* mask = (const float*)d_in[3];
    const float* Wku  = (const float*)d_in[4];
    const float* bku  = (const float*)d_in[5];
    const float* Wkw  = (const float*)d_in[6];
    const float* bkw  = (const float*)d_in[7];
    const float* Wfo  = (const float*)d_in[8];
    const float* bfo  = (const float*)d_in[9];
    const float* Wfw  = (const float*)d_in[10];
    const float* bfw  = (const float*)d_in[11];

    float* out = (float*)d_out;
    float* att_out = out + 1;
    float* avo_out = out + 1 + (size_t)Bw * Bo * Tw * To;

    bf16 *Kuhi = (bf16*)sym(Kuhi_g), *Kulo = (bf16*)sym(Kulo_g);
    bf16 *Kwhi = (bf16*)sym(Kwhi_g), *Kwlo = (bf16*)sym(Kwlo_g);
    bf16 *Vohi = (bf16*)sym(Vohi_g), *Volo = (bf16*)sym(Volo_g);
    float *pVw = (float*)sym(Vw_g), *pS = (float*)sym(S_g);

    cudaFuncSetAttribute(proj_grp_k, cudaFuncAttributeMaxDynamicSharedMemorySize, PROJ_SMEM);
    cudaFuncSetAttribute(s_mma_k,    cudaFuncAttributeMaxDynamicSharedMemorySize, S_SMEM);
    cudaFuncSetAttribute(av_fused_k, cudaFuncAttributeMaxDynamicSharedMemorySize, AV_SMEM);

    static cudaStream_t s1 = nullptr;
    static cudaEvent_t evFork = nullptr, evGrp1 = nullptr, evA = nullptr, evAvA = nullptr;
    if (s1 == nullptr) {
        cudaStreamCreateWithFlags(&s1, cudaStreamNonBlocking);
        cudaEventCreateWithFlags(&evFork, cudaEventDisableTiming);
        cudaEventCreateWithFlags(&evGrp1, cudaEventDisableTiming);
        cudaEventCreateWithFlags(&evA,    cudaEventDisableTiming);
        cudaEventCreateWithFlags(&evAvA,  cudaEventDisableTiming);
    }

    // stream 0: weight splits
    split_all_k<<<N4 / 256 + 1, 256>>>(Wku, Wkw, Wfo, Wfw);
    cudaEventRecord(evFork, 0);
    cudaStreamWaitEvent(s1, evFork, 0);

    // stream 1: zero logits + Vo/Vw projections
    zero_logits_k<<<(Bw * Bo * Tw) / 1024, 1024, 0, s1>>>();
    proj_grp_k<<<196, 256, PROJ_SMEM, s1>>>(u, o, w, bku, bkw, bfo, bfw, 1);
    cudaEventRecord(evGrp1, s1);

    // stream 0: Ku/Kw projections -> S band A (m-tiles 0..11)
    proj_grp_k<<<196, 256, PROJ_SMEM>>>(u, o, w, bku, bkw, bfo, bfw, 0);
    s_mma_k<<<dim3(75, 12), 256, S_SMEM>>>(Kwhi, Kwlo, Kuhi, Kulo, pS, Bw * Tw, Bo * To, Dk, 0);
    cudaEventRecord(evA, 0);

    // stream 1: AV band A overlaps S band B
    cudaStreamWaitEvent(s1, evA, 0);
    av_fused_k<<<dim3(12, 96), 512, AV_SMEM, s1>>>(pS, Vohi, Volo, pVw, att_out, avo_out, 0);
    cudaEventRecord(evAvA, s1);

    // stream 0: S band B (m-tiles 12..22) -> AV band B
    s_mma_k<<<dim3(75, 11), 256, S_SMEM>>>(Kwhi, Kwlo, Kuhi, Kulo, pS, Bw * Tw, Bo * To, Dk, 12);
    cudaStreamWaitEvent(0, evGrp1, 0);
    av_fused_k<<<dim3(11, 96), 512, AV_SMEM>>>(pS, Vohi, Volo, pVw, att_out, avo_out, 12);

    // loss (needs AV band A too)
    cudaStreamWaitEvent(0, evAvA, 0);
    loss_terms_k<<<(Bw * Tw) / 8, 256>>>(mask);
    loss_final_k<<<1, 256>>>(out);
}

// round 16
// speedup vs baseline: 1.0370x; 1.0175x over previous
#include <cuda_runtime.h>
#include <cuda_bf16.h>
#include <cstdint>

#define Bo 96
#define To 100
#define Do 1024
#define Bw 96
#define Tw 30
#define Dw 768
#define Du 2048
#define Dk 256
#define Dv 256

typedef __nv_bfloat16 bf16;

// ---------------- scratch ----------------
__device__ __align__(256) bf16 Wkuhi_g[Du * Dk], Wkulo_g[Du * Dk];
__device__ __align__(256) bf16 Wkwhi_g[Dw * Dk], Wkwlo_g[Dw * Dk];
__device__ __align__(256) bf16 Wfohi_g[Do * Dv], Wfolo_g[Do * Dv];
__device__ __align__(256) bf16 Wfwhi_g[Dw * Dv], Wfwlo_g[Dw * Dv];
__device__ __align__(256) bf16 Kuhi_g[(size_t)Bo * 128 * Dk], Kulo_g[(size_t)Bo * 128 * Dk]; // o pad 128
__device__ __align__(256) bf16 Kwhi_g[(size_t)Bw * Tw * Dk], Kwlo_g[(size_t)Bw * Tw * Dk];
__device__ __align__(256) bf16 Vohi_g[(size_t)Bo * 128 * Dv], Volo_g[(size_t)Bo * 128 * Dv]; // o pad 128
__device__ __align__(256) float Vw_g[(size_t)Bw * Tw * Dv];
__device__ __align__(256) float logits_g[(size_t)Bw * Bo * Tw];
__device__ __align__(256) float terms_g[(size_t)Bw * Tw];

// ---------------- helpers ----------------
__device__ __forceinline__ void ldsm_x4(uint32_t* r, uint32_t addr) {
    asm volatile("ldmatrix.sync.aligned.m8n8.x4.shared.b16 {%0,%1,%2,%3},[%4];"
                 : "=r"(r[0]), "=r"(r[1]), "=r"(r[2]), "=r"(r[3]) : "r"(addr));
}
__device__ __forceinline__ void ldsm_x4t(uint32_t* r, uint32_t addr) {
    asm volatile("ldmatrix.sync.aligned.m8n8.x4.trans.shared.b16 {%0,%1,%2,%3},[%4];"
                 : "=r"(r[0]), "=r"(r[1]), "=r"(r[2]), "=r"(r[3]) : "r"(addr));
}
__device__ __forceinline__ void mma16816(float* c, const uint32_t* a, uint32_t b0, uint32_t b1) {
    asm volatile("mma.sync.aligned.m16n8k16.row.col.f32.bf16.bf16.f32 "
                 "{%0,%1,%2,%3},{%4,%5,%6,%7},{%8,%9},{%0,%1,%2,%3};"
                 : "+f"(c[0]), "+f"(c[1]), "+f"(c[2]), "+f"(c[3])
                 : "r"(a[0]), "r"(a[1]), "r"(a[2]), "r"(a[3]), "r"(b0), "r"(b1));
}
__device__ __forceinline__ void cp16(uint32_t dst, const void* src) {
    asm volatile("cp.async.cg.shared.global [%0],[%1],16;" :: "r"(dst), "l"(src));
}
#define CP_COMMIT() asm volatile("cp.async.commit_group;")
#define CP_WAIT1()  asm volatile("cp.async.wait_group 1;")
#define CP_WAIT0()  asm volatile("cp.async.wait_group 0;")

__device__ __forceinline__ uint32_t pack2(float a, float b) {
    __nv_bfloat162 v = __floats2bfloat162_rn(a, b);
    return *(uint32_t*)&v;
}
__device__ __forceinline__ void split8(const float* f, uint32_t* hi, uint32_t* lo) {
#pragma unroll
    for (int j = 0; j < 4; j++) {
        bf16 h0 = __float2bfloat16(f[2 * j]);
        bf16 h1 = __float2bfloat16(f[2 * j + 1]);
        __nv_bfloat162 hv; hv.x = h0; hv.y = h1;
        hi[j] = *(uint32_t*)&hv;
        lo[j] = pack2(f[2 * j] - __bfloat162float(h0), f[2 * j + 1] - __bfloat162float(h1));
    }
}

// ---------------- merged weight split ----------------
#define N1 (Du * Dk / 4)
#define N2 (N1 + Dw * Dk / 4)
#define N3 (N2 + Do * Dv / 4)
#define N4 (N3 + Dw * Dv / 4)
__global__ __launch_bounds__(256) void split_all_k(
    const float* __restrict__ Wku, const float* __restrict__ Wkw,
    const float* __restrict__ Wfo, const float* __restrict__ Wfw)
{
    int i = blockIdx.x * 256 + threadIdx.x;
    if (i >= N4) return;
    const float* src; bf16 *hi, *lo; int j;
    if (i < N1)      { src = Wku; hi = Wkuhi_g; lo = Wkulo_g; j = i; }
    else if (i < N2) { src = Wkw; hi = Wkwhi_g; lo = Wkwlo_g; j = i - N1; }
    else if (i < N3) { src = Wfo; hi = Wfohi_g; lo = Wfolo_g; j = i - N2; }
    else             { src = Wfw; hi = Wfwhi_g; lo = Wfwlo_g; j = i - N3; }
    float4 v = ((const float4*)src)[j];
    float f[4] = {v.x, v.y, v.z, v.w};
    uint32_t h[2], l[2];
#pragma unroll
    for (int q = 0; q < 2; q++) {
        bf16 h0 = __float2bfloat16(f[2 * q]), h1 = __float2bfloat16(f[2 * q + 1]);
        __nv_bfloat162 hv; hv.x = h0; hv.y = h1;
        h[q] = *(uint32_t*)&hv;
        l[q] = pack2(f[2 * q] - __bfloat162float(h0), f[2 * q + 1] - __bfloat162float(h1));
    }
    ((uint32_t*)hi)[j * 2] = h[0]; ((uint32_t*)hi)[j * 2 + 1] = h[1];
    ((uint32_t*)lo)[j * 2] = l[0]; ((uint32_t*)lo)[j * 2 + 1] = l[1];
}

__global__ __launch_bounds__(1024) void zero_logits_k() {
    logits_g[blockIdx.x * 1024 + threadIdx.x] = 0.f;
}

// =====================================================================
// Projection GEMM, grouped (R13/R15 proven). Ku now ALSO padded-remap.
// grp 0: Ku (K=2048, remap) / Kw (K=768).  grp 1: Vo (K=1024, remap) / Vw.
// =====================================================================
#define PAS 5120
#define PBS 4352
#define PBBASE (6 * PAS)
#define PROJ_SMEM ((6 * PAS + 6 * PBS) * 2)   // 113664 B

__global__ __launch_bounds__(256, 2) void proj_grp_k(
    const float* __restrict__ u, const float* __restrict__ o, const float* __restrict__ w,
    const float* __restrict__ bku, const float* __restrict__ bkw,
    const float* __restrict__ bfo, const float* __restrict__ bfw,
    const int grp)
{
    extern __shared__ bf16 dyns[];
    const uint32_t sbase = (uint32_t)__cvta_generic_to_shared(dyns);
    const int N = 256;
    const int tid = threadIdx.x, lane = tid & 31, w8 = tid >> 5;
    const int wm = w8 & 3, wn = w8 >> 2;
    const int bid = blockIdx.x;

    const float* A; const bf16 *bhi, *blo; const float* bs;
    bf16 *Chi = nullptr, *Clo = nullptr; float* Cf = nullptr;
    int M, K, n0, m0, remap = 0; bool splitOut;

    if (bid < 150) {
        n0 = (bid & 1) * 128; m0 = (bid >> 1) * 128; M = Bo * To;
        if (grp == 0) {
            A = u; K = Du; bhi = Wkuhi_g; blo = Wkulo_g; bs = bku;
            Chi = Kuhi_g; Clo = Kulo_g; splitOut = true; remap = 1;
        } else {
            A = o; K = Do; bhi = Wfohi_g; blo = Wfolo_g; bs = bfo;
            Chi = Vohi_g; Clo = Volo_g; splitOut = true; remap = 1;
        }
    } else {
        int b2 = bid - 150;
        n0 = (b2 & 1) * 128; m0 = (b2 >> 1) * 128;
        A = w; K = Dw; M = Bw * Tw;
        if (grp == 0) {
            bhi = Wkwhi_g; blo = Wkwlo_g; bs = bkw;
            Chi = Kwhi_g; Clo = Kwlo_g; splitOut = true;
        } else {
            bhi = Wfwhi_g; blo = Wfwlo_g; bs = bfw; Cf = Vw_g; splitOut = false;
        }
    }

    const int akq = tid & 3, aml = tid >> 2;
    size_t abase[2];
#pragma unroll
    for (int p = 0; p < 2; p++) {
        int m = m0 + p * 64 + aml;
        if (m >= M) m = M - 1;
        abase[p] = (size_t)m * K;
    }
    const int bkr = tid >> 4, bnq = tid & 15;

    float rA[2][8];
    auto ldgA = [&](int k0) {
#pragma unroll
        for (int p = 0; p < 2; p++) {
            float4 v0 = *(const float4*)(A + abase[p] + k0 + akq * 8);
            float4 v1 = *(const float4*)(A + abase[p] + k0 + akq * 8 + 4);
            rA[p][0] = v0.x; rA[p][1] = v0.y; rA[p][2] = v0.z; rA[p][3] = v0.w;
            rA[p][4] = v1.x; rA[p][5] = v1.y; rA[p][6] = v1.z; rA[p][7] = v1.w;
        }
    };
    auto stsA = [&](int st) {
#pragma unroll
        for (int p = 0; p < 2; p++) {
            uint32_t hi[4], lo[4];
            split8(rA[p], hi, lo);
            int off = (p * 64 + aml) * 40 + akq * 8;
            *(uint4*)(dyns + (st * 2 + 0) * PAS + off) = make_uint4(hi[0], hi[1], hi[2], hi[3]);
            *(uint4*)(dyns + (st * 2 + 1) * PAS + off) = make_uint4(lo[0], lo[1], lo[2], lo[3]);
        }
    };
    auto cpB = [&](int k0, int st) {
#pragma unroll
        for (int hl = 0; hl < 2; hl++) {
            const bf16* bsrc = hl ? blo : bhi;
            uint32_t bbuf = sbase + (uint32_t)(PBBASE + (st * 2 + hl) * PBS) * 2;
#pragma unroll
            for (int p = 0; p < 2; p++) {
                int row = p * 16 + bkr;
                cp16(bbuf + (uint32_t)(row * 136 + bnq * 8) * 2,
                     bsrc + (size_t)(k0 + row) * N + n0 + bnq * 8);
            }
        }
    };

    float acc[2][8][4];
#pragma unroll
    for (int i = 0; i < 2; i++)
#pragma unroll
        for (int j = 0; j < 8; j++)
#pragma unroll
            for (int q = 0; q < 4; q++) acc[i][j][q] = 0.f;

    const int nsteps = K / 32;
    ldgA(0); stsA(0);
    cpB(0, 0); CP_COMMIT();
    cpB(32, 1); CP_COMMIT();
    ldgA(32);

    for (int s = 0; s < nsteps; s++) {
        if (s == nsteps - 1) { CP_WAIT0(); } else { CP_WAIT1(); }
        if (s + 1 < nsteps) stsA((s + 1) % 3);
        __syncthreads();
        if (s + 2 < nsteps) {
            ldgA((s + 2) * 32);
            cpB((s + 2) * 32, (s + 2) % 3); CP_COMMIT();
        }
        const int st = s % 3;
#pragma unroll
        for (int kk = 0; kk < 2; kk++) {
            uint32_t a[2][2][4];
            const int ar_ = (lane & 7) + ((lane >> 3) & 1) * 8;
            const int ac_ = kk * 16 + ((lane >> 4) << 3);
#pragma unroll
            for (int hl = 0; hl < 2; hl++)
#pragma unroll
                for (int mi = 0; mi < 2; mi++) {
                    int ar = wm * 32 + mi * 16 + ar_;
                    ldsm_x4(a[hl][mi], sbase + (uint32_t)((st * 2 + hl) * PAS + ar * 40 + ac_) * 2);
                }
#pragma unroll
            for (int ng = 0; ng < 4; ng++) {
                uint32_t bh[4], bl[4];
                int br = kk * 16 + (lane & 7) + ((lane >> 3) & 1) * 8;
                int bc = wn * 64 + ng * 16 + ((lane >> 4) << 3);
                ldsm_x4t(bh, sbase + (uint32_t)(PBBASE + (st * 2 + 0) * PBS + br * 136 + bc) * 2);
                ldsm_x4t(bl, sbase + (uint32_t)(PBBASE + (st * 2 + 1) * PBS + br * 136 + bc) * 2);
#pragma unroll
                for (int n2 = 0; n2 < 2; n2++) {
                    int ni = ng * 2 + n2;
#pragma unroll
                    for (int mi = 0; mi < 2; mi++) {
                        mma16816(acc[mi][ni], a[0][mi], bh[n2 * 2], bh[n2 * 2 + 1]);
                        mma16816(acc[mi][ni], a[0][mi], bl[n2 * 2], bl[n2 * 2 + 1]);
                        mma16816(acc[mi][ni], a[1][mi], bh[n2 * 2], bh[n2 * 2 + 1]);
                    }
                }
            }
        }
    }

    const int rbase = m0 + wm * 32 + (lane >> 2);
#pragma unroll
    for (int mi = 0; mi < 2; mi++)
#pragma unroll
        for (int ni = 0; ni < 8; ni++) {
            const int col = n0 + wn * 64 + ni * 8 + (lane & 3) * 2;
            float bv0 = bs[col], bv1 = bs[col + 1];
#pragma unroll
            for (int h = 0; h < 2; h++) {
                int r = rbase + mi * 16 + h * 8;
                if (r >= M) continue;
                float v0 = acc[mi][ni][h * 2 + 0] + bv0;
                float v1 = acc[mi][ni][h * 2 + 1] + bv1;
                if (splitOut) {
                    size_t orow = remap ? (size_t)(r / 100) * 128 + (r % 100) : (size_t)r;
                    bf16 h0 = __float2bfloat16(v0), h1 = __float2bfloat16(v1);
                    __nv_bfloat162 hv; hv.x = h0; hv.y = h1;
                    *(uint32_t*)(Chi + orow * 256 + col) = *(uint32_t*)&hv;
                    *(uint32_t*)(Clo + orow * 256 + col) =
                        pack2(v0 - __bfloat162float(h0), v1 - __bfloat162float(h1));
                } else {
                    float2 t; t.x = v0; t.y = v1;
                    *(float2*)(Cf + (size_t)r * N + col) = t;
                }
            }
        }
}

// =====================================================================
// FUSED S-GEMM + softmax + AV + logits. grid (23, 96), 512 threads.
// Phase 1: S = Kw[band] @ Ku[b]^T (K=256, 3-stage, 16 warps 4m x 4n,
//          skip wn==3/ng==1 pad quarter), scale 1/16 -> smem fp32.
// Phase 2: warp-per-row softmax from smem -> att + smem P hi/lo.
// Phase 3: AV = P @ Vo[b] (proven R12 loop) -> avo + logits atomics.
// smem (bf16 units): [0,26624) Sf32 | [26624,77312) Vo stages (6x8448)
//                    | [77312,112128) P hi/lo.  S stages [0,55296) reused.
// =====================================================================
#define F_SAST 9216
#define F_SB   (3 * F_SAST)
#define F_AVB  26624
#define F_PHI  77312
#define F_PLO  (F_PHI + 17408)
#define SAV_SMEM (112128 * 2)   // 224256 B

__global__ __launch_bounds__(512) void sav_k(
    const bf16* __restrict__ Awhi, const bf16* __restrict__ Awlo,   // Kw flat
    const bf16* __restrict__ Kup_hi, const bf16* __restrict__ Kup_lo, // Ku padded
    const bf16* __restrict__ Vhi, const bf16* __restrict__ Vlo,
    const float* __restrict__ Vw,
    float* __restrict__ att, float* __restrict__ avo)
{
    extern __shared__ bf16 dyns[];
    const uint32_t sbase = (uint32_t)__cvta_generic_to_shared(dyns);
    const int tid = threadIdx.x, lane = tid & 31, w16 = tid >> 5;
    const int wm = w16 & 3, wn = w16 >> 2;
    const int m0 = blockIdx.x * 128;
    const int bb = blockIdx.y;
    const int M = Bw * Tw;

    // ---------- phase 1: S tile ----------
    const int akq = tid & 3, arow = tid >> 2;   // 512 threads: 128 rows x 4 chunks
    int amr = m0 + arow; if (amr >= M) amr = M - 1;
    const size_t awoff = (size_t)amr * 256;
    const size_t kuoff = ((size_t)bb * 128 + arow) * 256;

    auto prefS = [&](int k0, int st) {
        uint32_t off = (uint32_t)(arow * 72 + akq * 8) * 2;
        uint32_t ab = sbase + (uint32_t)(st * F_SAST) * 2 + off;
        uint32_t bbuf = sbase + (uint32_t)(F_SB + st * F_SAST) * 2 + off;
        cp16(ab,      Awhi + awoff + k0 + akq * 8);
        cp16(ab + 64, Awlo + awoff + k0 + akq * 8);
        cp16(bbuf,      Kup_hi + kuoff + k0 + akq * 8);
        cp16(bbuf + 64, Kup_lo + kuoff + k0 + akq * 8);
    };

    {
        float sacc[2][4][4];
#pragma unroll
        for (int i = 0; i < 2; i++)
#pragma unroll
            for (int j = 0; j < 4; j++)
#pragma unroll
                for (int q = 0; q < 4; q++) sacc[i][j][q] = 0.f;

        prefS(0, 0); CP_COMMIT();
        prefS(32, 1); CP_COMMIT();

        for (int s = 0; s < 8; s++) {
            if (s == 7) { CP_WAIT0(); } else { CP_WAIT1(); }
            __syncthreads();
            if (s + 2 < 8) { prefS((s + 2) * 32, (s + 2) % 3); CP_COMMIT(); }
            const int st = s % 3;
#pragma unroll
            for (int kk = 0; kk < 2; kk++) {
                uint32_t a[2][2][4];
                const int ar_ = (lane & 7) + ((lane >> 3) & 1) * 8;
                const int ac_ = kk * 16 + ((lane >> 4) << 3);
#pragma unroll
                for (int hl = 0; hl < 2; hl++)
#pragma unroll
                    for (int mi = 0; mi < 2; mi++) {
                        int ar = wm * 32 + mi * 16 + ar_;
                        ldsm_x4(a[hl][mi],
                                sbase + (uint32_t)(st * F_SAST + ar * 72 + hl * 32 + ac_) * 2);
                    }
#pragma unroll
                for (int ng = 0; ng < 2; ng++) {
                    if (wn == 3 && ng == 1) continue;   // cols 112..127 are pad
                    uint32_t bh[4], bl[4];
                    int br = wn * 32 + ng * 16 + (lane & 7) + ((lane >> 4) << 3);
                    int bc = kk * 16 + ((lane >> 3) & 1) * 8;
                    ldsm_x4(bh, sbase + (uint32_t)(F_SB + st * F_SAST + br * 72 + bc) * 2);
                    ldsm_x4(bl, sbase + (uint32_t)(F_SB + st * F_SAST + br * 72 + 32 + bc) * 2);
#pragma unroll
                    for (int n2 = 0; n2 < 2; n2++) {
                        int ni = ng * 2 + n2;
#pragma unroll
                        for (int mi = 0; mi < 2; mi++) {
                            mma16816(sacc[mi][ni], a[0][mi], bh[n2 * 2], bh[n2 * 2 + 1]);
                            mma16816(sacc[mi][ni], a[0][mi], bl[n2 * 2], bl[n2 * 2 + 1]);
                            mma16816(sacc[mi][ni], a[1][mi], bh[n2 * 2], bh[n2 * 2 + 1]);
                        }
                    }
                }
            }
        }
        __syncthreads();   // S stages dead

        // store S tile (scaled) to smem fp32 [row][104]
        float* Sf = (float*)dyns;
        const int rb = wm * 32 + (lane >> 2);
#pragma unroll
        for (int mi = 0; mi < 2; mi++)
#pragma unroll
            for (int ni = 0; ni < 4; ni++) {
                if (wn == 3 && ni >= 2) continue;
                const int col = wn * 32 + ni * 8 + (lane & 3) * 2;
                if (col >= 100) continue;
#pragma unroll
                for (int h = 0; h < 2; h++) {
                    int row = rb + mi * 16 + h * 8;
                    float2 t;
                    t.x = sacc[mi][ni][h * 2 + 0] * 0.0625f;
                    t.y = sacc[mi][ni][h * 2 + 1] * 0.0625f;
                    *(float2*)(Sf + row * 104 + col) = t;
                }
            }
    }
    __syncthreads();

    // ---------- phase 2: Vo prefetch + softmax ----------
    auto cpB2 = [&](int k0, int st) {
#pragma unroll
        for (int hl = 0; hl < 2; hl++) {
            const bf16* bs = hl ? Vlo : Vhi;
            uint32_t bbuf = sbase + (uint32_t)(F_AVB + (st * 2 + hl) * 8448) * 2;
#pragma unroll
            for (int p = 0; p < 2; p++) {
                int idx = tid + p * 512;
                int row = idx >> 5, ch = idx & 31;
                cp16(bbuf + (uint32_t)(row * 264 + ch * 8) * 2,
                     bs + ((size_t)bb * 128 + k0 + row) * 256 + ch * 8);
            }
        }
    };
    cpB2(0, 0); CP_COMMIT();
    cpB2(32, 1); CP_COMMIT();

    const float* Sf = (const float*)dyns;
    for (int i = w16; i < 128; i += 16) {
        int m = m0 + i;
        float4 v = make_float4(-1e30f, -1e30f, -1e30f, -1e30f);
        if (lane < 25) v = *(const float4*)(Sf + i * 104 + lane * 4);

        float mx = fmaxf(fmaxf(v.x, v.y), fmaxf(v.z, v.w));
#pragma unroll
        for (int off = 16; off; off >>= 1) mx = fmaxf(mx, __shfl_xor_sync(0xffffffffu, mx, off));
        float4 e;
        e.x = __expf(v.x - mx); e.y = __expf(v.y - mx);
        e.z = __expf(v.z - mx); e.w = __expf(v.w - mx);
        float sm = e.x + e.y + e.z + e.w;
#pragma unroll
        for (int off = 16; off; off >>= 1) sm += __shfl_xor_sync(0xffffffffu, sm, off);
        const float inv = 1.f / sm;

        const int pb = F_PHI + i * 136 + lane * 4;
        if (lane < 25) {
            float r0 = e.x * inv, r1 = e.y * inv, r2 = e.z * inv, r3 = e.w * inv;
            if (m < M) {
                int w_ = m / 30, t_ = m - w_ * 30;
                float* dst = att + ((size_t)(w_ * 96 + bb) * 30 + t_) * 100 + lane * 4;
                dst[0] = r0; dst[1] = r1; dst[2] = r2; dst[3] = r3;
            }
            bf16 h0 = __float2bfloat16(r0), h1 = __float2bfloat16(r1);
            __nv_bfloat162 hv; hv.x = h0; hv.y = h1;
            *(uint32_t*)(dyns + pb) = *(uint32_t*)&hv;
            *(uint32_t*)(dyns + pb + (F_PLO - F_PHI)) =
                pack2(r0 - __bfloat162float(h0), r1 - __bfloat162float(h1));
            h0 = __float2bfloat16(r2); h1 = __float2bfloat16(r3);
            hv.x = h0; hv.y = h1;
            *(uint32_t*)(dyns + pb + 2) = *(uint32_t*)&hv;
            *(uint32_t*)(dyns + pb + (F_PLO - F_PHI) + 2) =
                pack2(r2 - __bfloat162float(h0), r3 - __bfloat162float(h1));
        } else {
            *(uint32_t*)(dyns + pb) = 0u;
            *(uint32_t*)(dyns + pb + 2) = 0u;
            *(uint32_t*)(dyns + pb + (F_PLO - F_PHI)) = 0u;
            *(uint32_t*)(dyns + pb + (F_PLO - F_PHI) + 2) = 0u;
        }
    }
    CP_WAIT1();
    __syncthreads();

    // ---------- phase 3: AV + logits ----------
    float acc[2][8][4];
#pragma unroll
    for (int i = 0; i < 2; i++)
#pragma unroll
        for (int j = 0; j < 8; j++)
#pragma unroll
            for (int q = 0; q < 4; q++) acc[i][j][q] = 0.f;

#pragma unroll
    for (int s = 0; s < 4; s++) {
        if (s > 0) {
            if (s == 3) { CP_WAIT0(); } else { CP_WAIT1(); }
            __syncthreads();
        }
        if (s + 2 < 4) { cpB2((s + 2) * 32, (s + 2) % 3); CP_COMMIT(); }
        const int st = s % 3;
#pragma unroll
        for (int kk = 0; kk < 2; kk++) {
            if (s == 3 && kk == 1) break;   // P cols 112..127 are zero
            uint32_t a[2][2][4];
            const int ar_ = (lane & 7) + ((lane >> 3) & 1) * 8;
            const int ac_ = s * 32 + kk * 16 + ((lane >> 4) << 3);
#pragma unroll
            for (int hl = 0; hl < 2; hl++)
#pragma unroll
                for (int mi = 0; mi < 2; mi++) {
                    int ar = wm * 32 + mi * 16 + ar_;
                    ldsm_x4(a[hl][mi],
                            sbase + (uint32_t)(F_PHI + hl * (F_PLO - F_PHI) + ar * 136 + ac_) * 2);
                }
#pragma unroll
            for (int ng = 0; ng < 4; ng++) {
                uint32_t bh[4], bl[4];
                int br = kk * 16 + (lane & 7) + ((lane >> 3) & 1) * 8;
                int bc = wn * 64 + ng * 16 + ((lane >> 4) << 3);
                ldsm_x4t(bh, sbase + (uint32_t)(F_AVB + (st * 2 + 0) * 8448 + br * 264 + bc) * 2);
                ldsm_x4t(bl, sbase + (uint32_t)(F_AVB + (st * 2 + 1) * 8448 + br * 264 + bc) * 2);
#pragma unroll
                for (int n2 = 0; n2 < 2; n2++) {
                    int ni = ng * 2 + n2;
#pragma unroll
                    for (int mi = 0; mi < 2; mi++) {
                        mma16816(acc[mi][ni], a[0][mi], bh[n2 * 2], bh[n2 * 2 + 1]);
                        mma16816(acc[mi][ni], a[0][mi], bl[n2 * 2], bl[n2 * 2 + 1]);
                        mma16816(acc[mi][ni], a[1][mi], bh[n2 * 2], bh[n2 * 2 + 1]);
                    }
                }
            }
        }
    }

    const int rbase = m0 + wm * 32 + (lane >> 2);
#pragma unroll
    for (int mi = 0; mi < 2; mi++)
#pragma unroll
        for (int h = 0; h < 2; h++) {
            int r = rbase + mi * 16 + h * 8;
            bool ok = (r < M);
            int rc = ok ? r : M - 1;
            int w_ = rc / 30, t_ = rc - w_ * 30;
            float* prow = avo + ((size_t)(w_ * 96 + bb) * 30 + t_) * 256;
            const float* vwrow = Vw + (size_t)(w_ * 30 + t_) * 256;
            float s = 0.f;
#pragma unroll
            for (int ni = 0; ni < 8; ni++) {
                const int col = wn * 64 + ni * 8 + (lane & 3) * 2;
                float v0 = acc[mi][ni][h * 2 + 0];
                float v1 = acc[mi][ni][h * 2 + 1];
                if (ok) { prow[col] = v0; prow[col + 1] = v1; }
                float2 vw2 = *(const float2*)(vwrow + col);
                s += v0 * vw2.x + v1 * vw2.y;
            }
            s += __shfl_xor_sync(0xffffffffu, s, 1);
            s += __shfl_xor_sync(0xffffffffu, s, 2);
            if (ok && (lane & 3) == 0)
                atomicAdd(&logits_g[(size_t)(w_ * 96 + bb) * 30 + t_], s);
        }
}

// ---------------- loss ----------------
__global__ __launch_bounds__(256) void loss_terms_k(const float* __restrict__ mask)
{
    const int idx = blockIdx.x * 8 + (threadIdx.x >> 5);
    const int w = idx / Tw, t = idx % Tw;
    const int lane = threadIdx.x & 31;

    float m = -1e30f;
    for (int b = lane; b < Bo; b += 32)
        m = fmaxf(m, logits_g[((size_t)w * Bo + b) * Tw + t]);
#pragma unroll
    for (int off = 16; off; off >>= 1) m = fmaxf(m, __shfl_xor_sync(0xffffffffu, m, off));

    float s = 0.f;
    for (int b = lane; b < Bo; b += 32)
        s += __expf(logits_g[((size_t)w * Bo + b) * Tw + t] - m);
#pragma unroll
    for (int off = 16; off; off >>= 1) s += __shfl_xor_sync(0xffffffffu, s, off);
    float lse = m + __logf(s);

    float nm = (lane < Tw) ? (1.f - mask[w * Tw + lane]) : 0.f;
#pragma unroll
    for (int off = 16; off; off >>= 1) nm += __shfl_xor_sync(0xffffffffu, nm, off);

    if (lane == 0) {
        float diag = logits_g[((size_t)w * Bo + w) * Tw + t];
        terms_g[w * Tw + t] = (1.f - mask[w * Tw + t]) * (diag - lse) / (nm + 1e-6f);
    }
}

__global__ __launch_bounds__(256) void loss_final_k(float* __restrict__ out)
{
    __shared__ float sh[256];
    float s = 0.f;
    for (int i = threadIdx.x; i < Bw * Tw; i += 256) s += terms_g[i];
    sh[threadIdx.x] = s;
    __syncthreads();
#pragma unroll
    for (int off = 128; off; off >>= 1) {
        if (threadIdx.x < off) sh[threadIdx.x] += sh[threadIdx.x + off];
        __syncthreads();
    }
    if (threadIdx.x == 0) out[0] = -sh[0] / (float)Bw;
}

// ---------------- launch ----------------
static inline void* sym(const void* s) { void* p; cudaGetSymbolAddress(&p, s); return p; }

extern "C" void kernel_launch(void* const* d_in, const int* in_sizes, int n_in,
                              void* d_out, int out_size)
{
    const float* o    = (const float*)d_in[0];
    const float* u    = (const float*)d_in[1];
    const float* w    = (const float*)d_in[2];
    const float* mask = (const float*)d_in[3];
    const float* Wku  = (const float*)d_in[4];
    const float* bku  = (const float*)d_in[5];
    const float* Wkw  = (const float*)d_in[6];
    const float* bkw  = (const float*)d_in[7];
    const float* Wfo  = (const float*)d_in[8];
    const float* bfo  = (const float*)d_in[9];
    const float* Wfw  = (const float*)d_in[10];
    const float* bfw  = (const float*)d_in[11];

    float* out = (float*)d_out;
    float* att_out = out + 1;
    float* avo_out = out + 1 + (size_t)Bw * Bo * Tw * To;

    bf16 *Kuhi = (bf16*)sym(Kuhi_g), *Kulo = (bf16*)sym(Kulo_g);
    bf16 *Kwhi = (bf16*)sym(Kwhi_g), *Kwlo = (bf16*)sym(Kwlo_g);
    bf16 *Vohi = (bf16*)sym(Vohi_g), *Volo = (bf16*)sym(Volo_g);
    float *pVw = (float*)sym(Vw_g);

    cudaFuncSetAttribute(proj_grp_k, cudaFuncAttributeMaxDynamicSharedMemorySize, PROJ_SMEM);
    cudaFuncSetAttribute(sav_k,      cudaFuncAttributeMaxDynamicSharedMemorySize, SAV_SMEM);

    static cudaStream_t s1 = nullptr;
    static cudaEvent_t evFork = nullptr, evGrp1 = nullptr;
    if (s1 == nullptr) {
        cudaStreamCreateWithFlags(&s1, cudaStreamNonBlocking);
        cudaEventCreateWithFlags(&evFork, cudaEventDisableTiming);
        cudaEventCreateWithFlags(&evGrp1, cudaEventDisableTiming);
    }

    // stream 0: weight splits
    split_all_k<<<N4 / 256 + 1, 256>>>(Wku, Wkw, Wfo, Wfw);
    cudaEventRecord(evFork, 0);
    cudaStreamWaitEvent(s1, evFork, 0);

    // stream 1: zero logits + Vo/Vw projections
    zero_logits_k<<<(Bw * Bo * Tw) / 1024, 1024, 0, s1>>>();
    proj_grp_k<<<196, 256, PROJ_SMEM, s1>>>(u, o, w, bku, bkw, bfo, bfw, 1);
    cudaEventRecord(evGrp1, s1);

    // stream 0: Ku/Kw projections
    proj_grp_k<<<196, 256, PROJ_SMEM>>>(u, o, w, bku, bkw, bfo, bfw, 0);

    // join, then fused S+softmax+AV+logits
    cudaStreamWaitEvent(0, evGrp1, 0);
    sav_k<<<dim3(23, 96), 512, SAV_SMEM>>>(Kwhi, Kwlo, Kuhi, Kulo, Vohi, Volo, pVw,
                                           att_out, avo_out);

    // loss
    loss_terms_k<<<(Bw * Tw) / 8, 256>>>(mask);
    loss_final_k<<<1, 256>>>(out);
}

// round 17
// speedup vs baseline: 1.0532x; 1.0156x over previous
#include <cuda_runtime.h>
#include <cuda_bf16.h>
#include <cstdint>

#define Bo 96
#define To 100
#define Do 1024
#define Bw 96
#define Tw 30
#define Dw 768
#define Du 2048
#define Dk 256
#define Dv 256

typedef __nv_bfloat16 bf16;

// ---------------- scratch ----------------
__device__ __align__(256) bf16 Wkuhi_g[Du * Dk], Wkulo_g[Du * Dk];
__device__ __align__(256) bf16 Wkwhi_g[Dw * Dk], Wkwlo_g[Dw * Dk];
__device__ __align__(256) bf16 Wfohi_g[Do * Dv], Wfolo_g[Do * Dv];
__device__ __align__(256) bf16 Wfwhi_g[Dw * Dv], Wfwlo_g[Dw * Dv];
__device__ __align__(256) bf16 Kuhi_g[(size_t)Bo * 128 * Dk], Kulo_g[(size_t)Bo * 128 * Dk]; // o pad 128
__device__ __align__(256) bf16 Kwhi_g[(size_t)Bw * Tw * Dk], Kwlo_g[(size_t)Bw * Tw * Dk];
__device__ __align__(256) bf16 Vohi_g[(size_t)Bo * 128 * Dv], Volo_g[(size_t)Bo * 128 * Dv]; // o pad 128
__device__ __align__(256) float Vw_g[(size_t)Bw * Tw * Dv];
__device__ __align__(256) float logits_g[(size_t)Bw * Bo * Tw];
__device__ __align__(256) float terms_g[(size_t)Bw * Tw];

// ---------------- helpers ----------------
__device__ __forceinline__ void ldsm_x4(uint32_t* r, uint32_t addr) {
    asm volatile("ldmatrix.sync.aligned.m8n8.x4.shared.b16 {%0,%1,%2,%3},[%4];"
                 : "=r"(r[0]), "=r"(r[1]), "=r"(r[2]), "=r"(r[3]) : "r"(addr));
}
__device__ __forceinline__ void ldsm_x4t(uint32_t* r, uint32_t addr) {
    asm volatile("ldmatrix.sync.aligned.m8n8.x4.trans.shared.b16 {%0,%1,%2,%3},[%4];"
                 : "=r"(r[0]), "=r"(r[1]), "=r"(r[2]), "=r"(r[3]) : "r"(addr));
}
__device__ __forceinline__ void mma16816(float* c, const uint32_t* a, uint32_t b0, uint32_t b1) {
    asm volatile("mma.sync.aligned.m16n8k16.row.col.f32.bf16.bf16.f32 "
                 "{%0,%1,%2,%3},{%4,%5,%6,%7},{%8,%9},{%0,%1,%2,%3};"
                 : "+f"(c[0]), "+f"(c[1]), "+f"(c[2]), "+f"(c[3])
                 : "r"(a[0]), "r"(a[1]), "r"(a[2]), "r"(a[3]), "r"(b0), "r"(b1));
}
__device__ __forceinline__ void cp16(uint32_t dst, const void* src) {
    asm volatile("cp.async.cg.shared.global [%0],[%1],16;" :: "r"(dst), "l"(src));
}
#define CP_COMMIT() asm volatile("cp.async.commit_group;")
#define CP_WAIT1()  asm volatile("cp.async.wait_group 1;")
#define CP_WAIT0()  asm volatile("cp.async.wait_group 0;")

__device__ __forceinline__ uint32_t pack2(float a, float b) {
    __nv_bfloat162 v = __floats2bfloat162_rn(a, b);
    return *(uint32_t*)&v;
}
__device__ __forceinline__ void split8(const float* f, uint32_t* hi, uint32_t* lo) {
#pragma unroll
    for (int j = 0; j < 4; j++) {
        bf16 h0 = __float2bfloat16(f[2 * j]);
        bf16 h1 = __float2bfloat16(f[2 * j + 1]);
        __nv_bfloat162 hv; hv.x = h0; hv.y = h1;
        hi[j] = *(uint32_t*)&hv;
        lo[j] = pack2(f[2 * j] - __bfloat162float(h0), f[2 * j + 1] - __bfloat162float(h1));
    }
}

// ---------------- merged weight split ----------------
#define N1 (Du * Dk / 4)
#define N2 (N1 + Dw * Dk / 4)
#define N3 (N2 + Do * Dv / 4)
#define N4 (N3 + Dw * Dv / 4)
__global__ __launch_bounds__(256) void split_all_k(
    const float* __restrict__ Wku, const float* __restrict__ Wkw,
    const float* __restrict__ Wfo, const float* __restrict__ Wfw)
{
    int i = blockIdx.x * 256 + threadIdx.x;
    if (i >= N4) return;
    const float* src; bf16 *hi, *lo; int j;
    if (i < N1)      { src = Wku; hi = Wkuhi_g; lo = Wkulo_g; j = i; }
    else if (i < N2) { src = Wkw; hi = Wkwhi_g; lo = Wkwlo_g; j = i - N1; }
    else if (i < N3) { src = Wfo; hi = Wfohi_g; lo = Wfolo_g; j = i - N2; }
    else             { src = Wfw; hi = Wfwhi_g; lo = Wfwlo_g; j = i - N3; }
    float4 v = ((const float4*)src)[j];
    float f[4] = {v.x, v.y, v.z, v.w};
    uint32_t h[2], l[2];
#pragma unroll
    for (int q = 0; q < 2; q++) {
        bf16 h0 = __float2bfloat16(f[2 * q]), h1 = __float2bfloat16(f[2 * q + 1]);
        __nv_bfloat162 hv; hv.x = h0; hv.y = h1;
        h[q] = *(uint32_t*)&hv;
        l[q] = pack2(f[2 * q] - __bfloat162float(h0), f[2 * q + 1] - __bfloat162float(h1));
    }
    ((uint32_t*)hi)[j * 2] = h[0]; ((uint32_t*)hi)[j * 2 + 1] = h[1];
    ((uint32_t*)lo)[j * 2] = l[0]; ((uint32_t*)lo)[j * 2 + 1] = l[1];
}

__global__ __launch_bounds__(1024) void zero_logits_k() {
    logits_g[blockIdx.x * 1024 + threadIdx.x] = 0.f;
}

// =====================================================================
// Merged projection GEMM (392 CTAs, ONE kernel) with COMPACT interleaved
// smem so 2 CTAs/SM pack (2 x 105984 = 211968 B):
//   A stage: 128 rows x [hi32|lo32|pad8]  (72 elems, 144B stride)
//   B stage: 32 k-rows x [hi128|lo128|pad8] (264 elems, 528B stride)
// bid<150: Ku (K=2048, remap). bid<300: Vo (K=1024, remap). else Kw/Vw.
// 3-stage single-sync ring.
// =====================================================================
#define PAST 9216
#define PBST 8448
#define PBBASE (3 * PAST)
#define PROJ_SMEM ((3 * PAST + 3 * PBST) * 2)   // 105984 B

__global__ __launch_bounds__(256, 2) void proj_all_k(
    const float* __restrict__ u, const float* __restrict__ o, const float* __restrict__ w,
    const float* __restrict__ bku, const float* __restrict__ bkw,
    const float* __restrict__ bfo, const float* __restrict__ bfw)
{
    extern __shared__ bf16 dyns[];
    const uint32_t sbase = (uint32_t)__cvta_generic_to_shared(dyns);
    const int N = 256;
    const int tid = threadIdx.x, lane = tid & 31, w8 = tid >> 5;
    const int wm = w8 & 3, wn = w8 >> 2;
    const int bid = blockIdx.x;

    const float* A; const bf16 *bhi, *blo; const float* bs;
    bf16 *Chi = nullptr, *Clo = nullptr; float* Cf = nullptr;
    int M, K, n0, m0, remap = 0; bool splitOut;

    if (bid < 150) {
        n0 = (bid & 1) * 128; m0 = (bid >> 1) * 128; M = Bo * To;
        A = u; K = Du; bhi = Wkuhi_g; blo = Wkulo_g; bs = bku;
        Chi = Kuhi_g; Clo = Kulo_g; splitOut = true; remap = 1;
    } else if (bid < 300) {
        int b2 = bid - 150;
        n0 = (b2 & 1) * 128; m0 = (b2 >> 1) * 128; M = Bo * To;
        A = o; K = Do; bhi = Wfohi_g; blo = Wfolo_g; bs = bfo;
        Chi = Vohi_g; Clo = Volo_g; splitOut = true; remap = 1;
    } else {
        int b2 = bid - 300;
        int bx = b2 & 3; m0 = (b2 >> 2) * 128;
        n0 = (bx & 1) * 128;
        A = w; K = Dw; M = Bw * Tw;
        if (bx < 2) { bhi = Wkwhi_g; blo = Wkwlo_g; bs = bkw; Chi = Kwhi_g; Clo = Kwlo_g; splitOut = true; }
        else        { bhi = Wfwhi_g; blo = Wfwlo_g; bs = bfw; Cf = Vw_g; splitOut = false; }
    }

    const int akq = tid & 3, aml = tid >> 2;
    size_t abase[2];
#pragma unroll
    for (int p = 0; p < 2; p++) {
        int m = m0 + p * 64 + aml;
        if (m >= M) m = M - 1;
        abase[p] = (size_t)m * K;
    }
    const int bkr = tid >> 4, bnq = tid & 15;

    float rA[2][8];
    auto ldgA = [&](int k0) {
#pragma unroll
        for (int p = 0; p < 2; p++) {
            float4 v0 = *(const float4*)(A + abase[p] + k0 + akq * 8);
            float4 v1 = *(const float4*)(A + abase[p] + k0 + akq * 8 + 4);
            rA[p][0] = v0.x; rA[p][1] = v0.y; rA[p][2] = v0.z; rA[p][3] = v0.w;
            rA[p][4] = v1.x; rA[p][5] = v1.y; rA[p][6] = v1.z; rA[p][7] = v1.w;
        }
    };
    auto stsA = [&](int st) {
#pragma unroll
        for (int p = 0; p < 2; p++) {
            uint32_t hi[4], lo[4];
            split8(rA[p], hi, lo);
            int off = st * PAST + (p * 64 + aml) * 72 + akq * 8;
            *(uint4*)(dyns + off)      = make_uint4(hi[0], hi[1], hi[2], hi[3]);
            *(uint4*)(dyns + off + 32) = make_uint4(lo[0], lo[1], lo[2], lo[3]);
        }
    };
    auto cpB = [&](int k0, int st) {
        uint32_t bbuf = sbase + (uint32_t)(PBBASE + st * PBST) * 2;
#pragma unroll
        for (int p = 0; p < 2; p++) {
            int row = p * 16 + bkr;
            cp16(bbuf + (uint32_t)(row * 264 + bnq * 8) * 2,
                 bhi + (size_t)(k0 + row) * N + n0 + bnq * 8);
            cp16(bbuf + (uint32_t)(row * 264 + 128 + bnq * 8) * 2,
                 blo + (size_t)(k0 + row) * N + n0 + bnq * 8);
        }
    };

    float acc[2][8][4];
#pragma unroll
    for (int i = 0; i < 2; i++)
#pragma unroll
        for (int j = 0; j < 8; j++)
#pragma unroll
            for (int q = 0; q < 4; q++) acc[i][j][q] = 0.f;

    const int nsteps = K / 32;
    ldgA(0); stsA(0);
    cpB(0, 0); CP_COMMIT();
    cpB(32, 1); CP_COMMIT();
    ldgA(32);

    for (int s = 0; s < nsteps; s++) {
        if (s == nsteps - 1) { CP_WAIT0(); } else { CP_WAIT1(); }
        if (s + 1 < nsteps) stsA((s + 1) % 3);
        __syncthreads();
        if (s + 2 < nsteps) {
            ldgA((s + 2) * 32);
            cpB((s + 2) * 32, (s + 2) % 3); CP_COMMIT();
        }
        const int st = s % 3;
#pragma unroll
        for (int kk = 0; kk < 2; kk++) {
            uint32_t a[2][2][4];
            const int ar_ = (lane & 7) + ((lane >> 3) & 1) * 8;
            const int ac_ = kk * 16 + ((lane >> 4) << 3);
#pragma unroll
            for (int hl = 0; hl < 2; hl++)
#pragma unroll
                for (int mi = 0; mi < 2; mi++) {
                    int ar = wm * 32 + mi * 16 + ar_;
                    ldsm_x4(a[hl][mi],
                            sbase + (uint32_t)(st * PAST + ar * 72 + hl * 32 + ac_) * 2);
                }
#pragma unroll
            for (int ng = 0; ng < 4; ng++) {
                uint32_t bh[4], bl[4];
                int br = kk * 16 + (lane & 7) + ((lane >> 3) & 1) * 8;
                int bc = wn * 64 + ng * 16 + ((lane >> 4) << 3);
                ldsm_x4t(bh, sbase + (uint32_t)(PBBASE + st * PBST + br * 264 + bc) * 2);
                ldsm_x4t(bl, sbase + (uint32_t)(PBBASE + st * PBST + br * 264 + 128 + bc) * 2);
#pragma unroll
                for (int n2 = 0; n2 < 2; n2++) {
                    int ni = ng * 2 + n2;
#pragma unroll
                    for (int mi = 0; mi < 2; mi++) {
                        mma16816(acc[mi][ni], a[0][mi], bh[n2 * 2], bh[n2 * 2 + 1]);
                        mma16816(acc[mi][ni], a[0][mi], bl[n2 * 2], bl[n2 * 2 + 1]);
                        mma16816(acc[mi][ni], a[1][mi], bh[n2 * 2], bh[n2 * 2 + 1]);
                    }
                }
            }
        }
    }

    const int rbase = m0 + wm * 32 + (lane >> 2);
#pragma unroll
    for (int mi = 0; mi < 2; mi++)
#pragma unroll
        for (int ni = 0; ni < 8; ni++) {
            const int col = n0 + wn * 64 + ni * 8 + (lane & 3) * 2;
            float bv0 = bs[col], bv1 = bs[col + 1];
#pragma unroll
            for (int h = 0; h < 2; h++) {
                int r = rbase + mi * 16 + h * 8;
                if (r >= M) continue;
                float v0 = acc[mi][ni][h * 2 + 0] + bv0;
                float v1 = acc[mi][ni][h * 2 + 1] + bv1;
                if (splitOut) {
                    size_t orow = remap ? (size_t)(r / 100) * 128 + (r % 100) : (size_t)r;
                    bf16 h0 = __float2bfloat16(v0), h1 = __float2bfloat16(v1);
                    __nv_bfloat162 hv; hv.x = h0; hv.y = h1;
                    *(uint32_t*)(Chi + orow * 256 + col) = *(uint32_t*)&hv;
                    *(uint32_t*)(Clo + orow * 256 + col) =
                        pack2(v0 - __bfloat162float(h0), v1 - __bfloat162float(h1));
                } else {
                    float2 t; t.x = v0; t.y = v1;
                    *(float2*)(Cf + (size_t)r * N + col) = t;
                }
            }
        }
}

// =====================================================================
// FUSED S-GEMM + softmax + AV + logits (proven R16). grid (23, 96), 512 thr.
// =====================================================================
#define F_SAST 9216
#define F_SB   (3 * F_SAST)
#define F_AVB  26624
#define F_PHI  77312
#define F_PLO  (F_PHI + 17408)
#define SAV_SMEM (112128 * 2)   // 224256 B

__global__ __launch_bounds__(512) void sav_k(
    const bf16* __restrict__ Awhi, const bf16* __restrict__ Awlo,
    const bf16* __restrict__ Kup_hi, const bf16* __restrict__ Kup_lo,
    const bf16* __restrict__ Vhi, const bf16* __restrict__ Vlo,
    const float* __restrict__ Vw,
    float* __restrict__ att, float* __restrict__ avo)
{
    extern __shared__ bf16 dyns[];
    const uint32_t sbase = (uint32_t)__cvta_generic_to_shared(dyns);
    const int tid = threadIdx.x, lane = tid & 31, w16 = tid >> 5;
    const int wm = w16 & 3, wn = w16 >> 2;
    const int m0 = blockIdx.x * 128;
    const int bb = blockIdx.y;
    const int M = Bw * Tw;

    // ---------- phase 1: S tile ----------
    const int akq = tid & 3, arow = tid >> 2;
    int amr = m0 + arow; if (amr >= M) amr = M - 1;
    const size_t awoff = (size_t)amr * 256;
    const size_t kuoff = ((size_t)bb * 128 + arow) * 256;

    auto prefS = [&](int k0, int st) {
        uint32_t off = (uint32_t)(arow * 72 + akq * 8) * 2;
        uint32_t ab = sbase + (uint32_t)(st * F_SAST) * 2 + off;
        uint32_t bbuf = sbase + (uint32_t)(F_SB + st * F_SAST) * 2 + off;
        cp16(ab,      Awhi + awoff + k0 + akq * 8);
        cp16(ab + 64, Awlo + awoff + k0 + akq * 8);
        cp16(bbuf,      Kup_hi + kuoff + k0 + akq * 8);
        cp16(bbuf + 64, Kup_lo + kuoff + k0 + akq * 8);
    };

    {
        float sacc[2][4][4];
#pragma unroll
        for (int i = 0; i < 2; i++)
#pragma unroll
            for (int j = 0; j < 4; j++)
#pragma unroll
                for (int q = 0; q < 4; q++) sacc[i][j][q] = 0.f;

        prefS(0, 0); CP_COMMIT();
        prefS(32, 1); CP_COMMIT();

        for (int s = 0; s < 8; s++) {
            if (s == 7) { CP_WAIT0(); } else { CP_WAIT1(); }
            __syncthreads();
            if (s + 2 < 8) { prefS((s + 2) * 32, (s + 2) % 3); CP_COMMIT(); }
            const int st = s % 3;
#pragma unroll
            for (int kk = 0; kk < 2; kk++) {
                uint32_t a[2][2][4];
                const int ar_ = (lane & 7) + ((lane >> 3) & 1) * 8;
                const int ac_ = kk * 16 + ((lane >> 4) << 3);
#pragma unroll
                for (int hl = 0; hl < 2; hl++)
#pragma unroll
                    for (int mi = 0; mi < 2; mi++) {
                        int ar = wm * 32 + mi * 16 + ar_;
                        ldsm_x4(a[hl][mi],
                                sbase + (uint32_t)(st * F_SAST + ar * 72 + hl * 32 + ac_) * 2);
                    }
#pragma unroll
                for (int ng = 0; ng < 2; ng++) {
                    if (wn == 3 && ng == 1) continue;
                    uint32_t bh[4], bl[4];
                    int br = wn * 32 + ng * 16 + (lane & 7) + ((lane >> 4) << 3);
                    int bc = kk * 16 + ((lane >> 3) & 1) * 8;
                    ldsm_x4(bh, sbase + (uint32_t)(F_SB + st * F_SAST + br * 72 + bc) * 2);
                    ldsm_x4(bl, sbase + (uint32_t)(F_SB + st * F_SAST + br * 72 + 32 + bc) * 2);
#pragma unroll
                    for (int n2 = 0; n2 < 2; n2++) {
                        int ni = ng * 2 + n2;
#pragma unroll
                        for (int mi = 0; mi < 2; mi++) {
                            mma16816(sacc[mi][ni], a[0][mi], bh[n2 * 2], bh[n2 * 2 + 1]);
                            mma16816(sacc[mi][ni], a[0][mi], bl[n2 * 2], bl[n2 * 2 + 1]);
                            mma16816(sacc[mi][ni], a[1][mi], bh[n2 * 2], bh[n2 * 2 + 1]);
                        }
                    }
                }
            }
        }
        __syncthreads();

        float* Sf = (float*)dyns;
        const int rb = wm * 32 + (lane >> 2);
#pragma unroll
        for (int mi = 0; mi < 2; mi++)
#pragma unroll
            for (int ni = 0; ni < 4; ni++) {
                if (wn == 3 && ni >= 2) continue;
                const int col = wn * 32 + ni * 8 + (lane & 3) * 2;
                if (col >= 100) continue;
#pragma unroll
                for (int h = 0; h < 2; h++) {
                    int row = rb + mi * 16 + h * 8;
                    float2 t;
                    t.x = sacc[mi][ni][h * 2 + 0] * 0.0625f;
                    t.y = sacc[mi][ni][h * 2 + 1] * 0.0625f;
                    *(float2*)(Sf + row * 104 + col) = t;
                }
            }
    }
    __syncthreads();

    // ---------- phase 2: Vo prefetch + softmax ----------
    auto cpB2 = [&](int k0, int st) {
#pragma unroll
        for (int hl = 0; hl < 2; hl++) {
            const bf16* bs = hl ? Vlo : Vhi;
            uint32_t bbuf = sbase + (uint32_t)(F_AVB + (st * 2 + hl) * 8448) * 2;
#pragma unroll
            for (int p = 0; p < 2; p++) {
                int idx = tid + p * 512;
                int row = idx >> 5, ch = idx & 31;
                cp16(bbuf + (uint32_t)(row * 264 + ch * 8) * 2,
                     bs + ((size_t)bb * 128 + k0 + row) * 256 + ch * 8);
            }
        }
    };
    cpB2(0, 0); CP_COMMIT();
    cpB2(32, 1); CP_COMMIT();

    const float* Sf = (const float*)dyns;
    for (int i = w16; i < 128; i += 16) {
        int m = m0 + i;
        float4 v = make_float4(-1e30f, -1e30f, -1e30f, -1e30f);
        if (lane < 25) v = *(const float4*)(Sf + i * 104 + lane * 4);

        float mx = fmaxf(fmaxf(v.x, v.y), fmaxf(v.z, v.w));
#pragma unroll
        for (int off = 16; off; off >>= 1) mx = fmaxf(mx, __shfl_xor_sync(0xffffffffu, mx, off));
        float4 e;
        e.x = __expf(v.x - mx); e.y = __expf(v.y - mx);
        e.z = __expf(v.z - mx); e.w = __expf(v.w - mx);
        float sm = e.x + e.y + e.z + e.w;
#pragma unroll
        for (int off = 16; off; off >>= 1) sm += __shfl_xor_sync(0xffffffffu, sm, off);
        const float inv = 1.f / sm;

        const int pb = F_PHI + i * 136 + lane * 4;
        if (lane < 25) {
            float r0 = e.x * inv, r1 = e.y * inv, r2 = e.z * inv, r3 = e.w * inv;
            if (m < M) {
                int w_ = m / 30, t_ = m - w_ * 30;
                float* dst = att + ((size_t)(w_ * 96 + bb) * 30 + t_) * 100 + lane * 4;
                dst[0] = r0; dst[1] = r1; dst[2] = r2; dst[3] = r3;
            }
            bf16 h0 = __float2bfloat16(r0), h1 = __float2bfloat16(r1);
            __nv_bfloat162 hv; hv.x = h0; hv.y = h1;
            *(uint32_t*)(dyns + pb) = *(uint32_t*)&hv;
            *(uint32_t*)(dyns + pb + (F_PLO - F_PHI)) =
                pack2(r0 - __bfloat162float(h0), r1 - __bfloat162float(h1));
            h0 = __float2bfloat16(r2); h1 = __float2bfloat16(r3);
            hv.x = h0; hv.y = h1;
            *(uint32_t*)(dyns + pb + 2) = *(uint32_t*)&hv;
            *(uint32_t*)(dyns + pb + (F_PLO - F_PHI) + 2) =
                pack2(r2 - __bfloat162float(h0), r3 - __bfloat162float(h1));
        } else {
            *(uint32_t*)(dyns + pb) = 0u;
            *(uint32_t*)(dyns + pb + 2) = 0u;
            *(uint32_t*)(dyns + pb + (F_PLO - F_PHI)) = 0u;
            *(uint32_t*)(dyns + pb + (F_PLO - F_PHI) + 2) = 0u;
        }
    }
    CP_WAIT1();
    __syncthreads();

    // ---------- phase 3: AV + logits ----------
    float acc[2][8][4];
#pragma unroll
    for (int i = 0; i < 2; i++)
#pragma unroll
        for (int j = 0; j < 8; j++)
#pragma unroll
            for (int q = 0; q < 4; q++) acc[i][j][q] = 0.f;

#pragma unroll
    for (int s = 0; s < 4; s++) {
        if (s > 0) {
            if (s == 3) { CP_WAIT0(); } else { CP_WAIT1(); }
            __syncthreads();
        }
        if (s + 2 < 4) { cpB2((s + 2) * 32, (s + 2) % 3); CP_COMMIT(); }
        const int st = s % 3;
#pragma unroll
        for (int kk = 0; kk < 2; kk++) {
            if (s == 3 && kk == 1) break;
            uint32_t a[2][2][4];
            const int ar_ = (lane & 7) + ((lane >> 3) & 1) * 8;
            const int ac_ = s * 32 + kk * 16 + ((lane >> 4) << 3);
#pragma unroll
            for (int hl = 0; hl < 2; hl++)
#pragma unroll
                for (int mi = 0; mi < 2; mi++) {
                    int ar = wm * 32 + mi * 16 + ar_;
                    ldsm_x4(a[hl][mi],
                            sbase + (uint32_t)(F_PHI + hl * (F_PLO - F_PHI) + ar * 136 + ac_) * 2);
                }
#pragma unroll
            for (int ng = 0; ng < 4; ng++) {
                uint32_t bh[4], bl[4];
                int br = kk * 16 + (lane & 7) + ((lane >> 3) & 1) * 8;
                int bc = wn * 64 + ng * 16 + ((lane >> 4) << 3);
                ldsm_x4t(bh, sbase + (uint32_t)(F_AVB + (st * 2 + 0) * 8448 + br * 264 + bc) * 2);
                ldsm_x4t(bl, sbase + (uint32_t)(F_AVB + (st * 2 + 1) * 8448 + br * 264 + bc) * 2);
#pragma unroll
                for (int n2 = 0; n2 < 2; n2++) {
                    int ni = ng * 2 + n2;
#pragma unroll
                    for (int mi = 0; mi < 2; mi++) {
                        mma16816(acc[mi][ni], a[0][mi], bh[n2 * 2], bh[n2 * 2 + 1]);
                        mma16816(acc[mi][ni], a[0][mi], bl[n2 * 2], bl[n2 * 2 + 1]);
                        mma16816(acc[mi][ni], a[1][mi], bh[n2 * 2], bh[n2 * 2 + 1]);
                    }
                }
            }
        }
    }

    const int rbase = m0 + wm * 32 + (lane >> 2);
#pragma unroll
    for (int mi = 0; mi < 2; mi++)
#pragma unroll
        for (int h = 0; h < 2; h++) {
            int r = rbase + mi * 16 + h * 8;
            bool ok = (r < M);
            int rc = ok ? r : M - 1;
            int w_ = rc / 30, t_ = rc - w_ * 30;
            float* prow = avo + ((size_t)(w_ * 96 + bb) * 30 + t_) * 256;
            const float* vwrow = Vw + (size_t)(w_ * 30 + t_) * 256;
            float s = 0.f;
#pragma unroll
            for (int ni = 0; ni < 8; ni++) {
                const int col = wn * 64 + ni * 8 + (lane & 3) * 2;
                float v0 = acc[mi][ni][h * 2 + 0];
                float v1 = acc[mi][ni][h * 2 + 1];
                if (ok) { prow[col] = v0; prow[col + 1] = v1; }
                float2 vw2 = *(const float2*)(vwrow + col);
                s += v0 * vw2.x + v1 * vw2.y;
            }
            s += __shfl_xor_sync(0xffffffffu, s, 1);
            s += __shfl_xor_sync(0xffffffffu, s, 2);
            if (ok && (lane & 3) == 0)
                atomicAdd(&logits_g[(size_t)(w_ * 96 + bb) * 30 + t_], s);
        }
}

// ---------------- loss ----------------
__global__ __launch_bounds__(256) void loss_terms_k(const float* __restrict__ mask)
{
    const int idx = blockIdx.x * 8 + (threadIdx.x >> 5);
    const int w = idx / Tw, t = idx % Tw;
    const int lane = threadIdx.x & 31;

    float m = -1e30f;
    for (int b = lane; b < Bo; b += 32)
        m = fmaxf(m, logits_g[((size_t)w * Bo + b) * Tw + t]);
#pragma unroll
    for (int off = 16; off; off >>= 1) m = fmaxf(m, __shfl_xor_sync(0xffffffffu, m, off));

    float s = 0.f;
    for (int b = lane; b < Bo; b += 32)
        s += __expf(logits_g[((size_t)w * Bo + b) * Tw + t] - m);
#pragma unroll
    for (int off = 16; off; off >>= 1) s += __shfl_xor_sync(0xffffffffu, s, off);
    float lse = m + __logf(s);

    float nm = (lane < Tw) ? (1.f - mask[w * Tw + lane]) : 0.f;
#pragma unroll
    for (int off = 16; off; off >>= 1) nm += __shfl_xor_sync(0xffffffffu, nm, off);

    if (lane == 0) {
        float diag = logits_g[((size_t)w * Bo + w) * Tw + t];
        terms_g[w * Tw + t] = (1.f - mask[w * Tw + t]) * (diag - lse) / (nm + 1e-6f);
    }
}

__global__ __launch_bounds__(256) void loss_final_k(float* __restrict__ out)
{
    __shared__ float sh[256];
    float s = 0.f;
    for (int i = threadIdx.x; i < Bw * Tw; i += 256) s += terms_g[i];
    sh[threadIdx.x] = s;
    __syncthreads();
#pragma unroll
    for (int off = 128; off; off >>= 1) {
        if (threadIdx.x < off) sh[threadIdx.x] += sh[threadIdx.x + off];
        __syncthreads();
    }
    if (threadIdx.x == 0) out[0] = -sh[0] / (float)Bw;
}

// ---------------- launch ----------------
static inline void* sym(const void* s) { void* p; cudaGetSymbolAddress(&p, s); return p; }

extern "C" void kernel_launch(void* const* d_in, const int* in_sizes, int n_in,
                              void* d_out, int out_size)
{
    const float* o    = (const float*)d_in[0];
    const float* u    = (const float*)d_in[1];
    const float* w    = (const float*)d_in[2];
    const float* mask = (const float*)d_in[3];
    const float* Wku  = (const float*)d_in[4];
    const float* bku  = (const float*)d_in[5];
    const float* Wkw  = (const float*)d_in[6];
    const float* bkw  = (const float*)d_in[7];
    const float* Wfo  = (const float*)d_in[8];
    const float* bfo  = (const float*)d_in[9];
    const float* Wfw  = (const float*)d_in[10];
    const float* bfw  = (const float*)d_in[11];

    float* out = (float*)d_out;
    float* att_out = out + 1;
    float* avo_out = out + 1 + (size_t)Bw * Bo * Tw * To;

    bf16 *Kuhi = (bf16*)sym(Kuhi_g), *Kulo = (bf16*)sym(Kulo_g);
    bf16 *Kwhi = (bf16*)sym(Kwhi_g), *Kwlo = (bf16*)sym(Kwlo_g);
    bf16 *Vohi = (bf16*)sym(Vohi_g), *Volo = (bf16*)sym(Volo_g);
    float *pVw = (float*)sym(Vw_g);

    cudaFuncSetAttribute(proj_all_k, cudaFuncAttributeMaxDynamicSharedMemorySize, PROJ_SMEM);
    cudaFuncSetAttribute(sav_k,      cudaFuncAttributeMaxDynamicSharedMemorySize, SAV_SMEM);

    static cudaStream_t s1 = nullptr;
    static cudaEvent_t evFork = nullptr, evZero = nullptr;
    if (s1 == nullptr) {
        cudaStreamCreateWithFlags(&s1, cudaStreamNonBlocking);
        cudaEventCreateWithFlags(&evFork, cudaEventDisableTiming);
        cudaEventCreateWithFlags(&evZero, cudaEventDisableTiming);
    }

    // stream 0: weight splits
    split_all_k<<<N4 / 256 + 1, 256>>>(Wku, Wkw, Wfo, Wfw);
    cudaEventRecord(evFork, 0);
    cudaStreamWaitEvent(s1, evFork, 0);

    // stream 1: zero logits (overlaps proj)
    zero_logits_k<<<(Bw * Bo * Tw) / 1024, 1024, 0, s1>>>();
    cudaEventRecord(evZero, s1);

    // stream 0: ALL projections, one kernel, 2 CTAs/SM
    proj_all_k<<<392, 256, PROJ_SMEM>>>(u, o, w, bku, bkw, bfo, bfw);

    // fused S+softmax+AV+logits
    cudaStreamWaitEvent(0, evZero, 0);
    sav_k<<<dim3(23, 96), 512, SAV_SMEM>>>(Kwhi, Kwlo, Kuhi, Kulo, Vohi, Volo, pVw,
                                           att_out, avo_out);

    // loss
    loss_terms_k<<<(Bw * Tw) / 8, 256>>>(mask);
    loss_final_k<<<1, 256>>>(out);
}